// round 1
// baseline (speedup 1.0000x reference)
#include <cuda_runtime.h>

#define D      128
#define NROW   50000
#define NCOL   50000
#define BM     128

// Scratch (alloc-free rule: __device__ globals)
__device__ float g_agg [(size_t)NROW * D];   // reused for both aggregation passes
__device__ float g_hrow[(size_t)NROW * D];   // h_row needed by second gather

__device__ __forceinline__ float leaky(float v) { return v >= 0.f ? v : 0.01f * v; }

__global__ void zero_kernel(float4* __restrict__ p, int n4) {
    int i = blockIdx.x * blockDim.x + threadIdx.x;
    if (i < n4) p[i] = make_float4(0.f, 0.f, 0.f, 0.f);
}

// One warp per edge; each lane handles one float4 (4 of 128 dims).
__global__ void agg_kernel(const float4* __restrict__ feat,
                           const int* __restrict__ src,
                           const int* __restrict__ dst,
                           const float* __restrict__ w,
                           float* __restrict__ agg, int E) {
    long long t = (long long)blockIdx.x * blockDim.x + threadIdx.x;
    int e = (int)(t >> 5);
    if (e >= E) return;
    int lane = (int)(t & 31);
    int s = __ldg(src + e);
    int d = __ldg(dst + e);
    float wt = __ldg(w + e);
    float4 v = __ldg(feat + (size_t)s * 32 + lane);
    float* a = agg + (size_t)d * D + lane * 4;
    atomicAdd(a + 0, v.x * wt);
    atomicAdd(a + 1, v.y * wt);
    atomicAdd(a + 2, v.z * wt);
    atomicAdd(a + 3, v.w * wt);
}

// Fused 2-layer MLP + bias + LeakyReLU + residual.
// Block: 256 threads, BM=128 rows. Thread microtile 8 rows x 8 cols.
// smem: xb[BM*D] row-major activations, ws[D*D] current weight matrix.
__global__ void __launch_bounds__(256, 1)
mlp_kernel(const float* __restrict__ feat, const float* __restrict__ agg,
           const float* __restrict__ W1, const float* __restrict__ b1,
           const float* __restrict__ W2, const float* __restrict__ b2,
           const float* __restrict__ eps_p,
           float* __restrict__ h_out, float* __restrict__ out, int N) {
    extern __shared__ float sm[];
    float* xb = sm;            // BM*D floats (row-major)
    float* ws = sm + BM * D;   // D*D floats (row-major [k][j])

    const int tid = threadIdx.x;
    const int tx = tid & 15;      // 16 col-groups of 8
    const int ty = tid >> 4;      // 16 row-groups of 8
    const int row0 = blockIdx.x * BM;
    const float eps1 = 1.f + *eps_p;

    const float4* feat4 = (const float4*)feat;
    const float4* agg4  = (const float4*)agg;

    // ---- stage x = (1+eps)*feat + agg, and W1 ----
    #pragma unroll
    for (int i = 0; i < 16; i++) {
        int idx = tid + i * 256;           // 4096 float4 = BM*D floats
        int r   = idx >> 5;                // row in block
        int grow = row0 + r;
        float4 v = make_float4(0.f, 0.f, 0.f, 0.f);
        if (grow < N) {
            float4 f = __ldg(feat4 + (size_t)grow * 32 + (idx & 31));
            float4 a = __ldg(agg4  + (size_t)grow * 32 + (idx & 31));
            v.x = fmaf(eps1, f.x, a.x);
            v.y = fmaf(eps1, f.y, a.y);
            v.z = fmaf(eps1, f.z, a.z);
            v.w = fmaf(eps1, f.w, a.w);
        }
        ((float4*)xb)[idx] = v;
    }
    const float4* W14 = (const float4*)W1;
    #pragma unroll
    for (int i = 0; i < 16; i++) {
        int idx = tid + i * 256;
        ((float4*)ws)[idx] = __ldg(W14 + idx);
    }
    // biases into registers
    float bv1[8], bv2[8];
    {
        float4 a = ((const float4*)b1)[tx * 2], b = ((const float4*)b1)[tx * 2 + 1];
        bv1[0]=a.x; bv1[1]=a.y; bv1[2]=a.z; bv1[3]=a.w;
        bv1[4]=b.x; bv1[5]=b.y; bv1[6]=b.z; bv1[7]=b.w;
        float4 c = ((const float4*)b2)[tx * 2], d = ((const float4*)b2)[tx * 2 + 1];
        bv2[0]=c.x; bv2[1]=c.y; bv2[2]=c.z; bv2[3]=c.w;
        bv2[4]=d.x; bv2[5]=d.y; bv2[6]=d.z; bv2[7]=d.w;
    }
    __syncthreads();

    // ---- layer 1 ----
    float acc[8][8];
    #pragma unroll
    for (int r = 0; r < 8; r++)
        #pragma unroll
        for (int c = 0; c < 8; c++) acc[r][c] = 0.f;

    #pragma unroll 4
    for (int k = 0; k < D; k++) {
        float xr[8];
        #pragma unroll
        for (int r = 0; r < 8; r++) xr[r] = xb[(ty * 8 + r) * D + k];
        float4 wa = ((const float4*)(ws + k * D))[tx * 2];
        float4 wb = ((const float4*)(ws + k * D))[tx * 2 + 1];
        float wv[8] = {wa.x, wa.y, wa.z, wa.w, wb.x, wb.y, wb.z, wb.w};
        #pragma unroll
        for (int r = 0; r < 8; r++)
            #pragma unroll
            for (int c = 0; c < 8; c++) acc[r][c] = fmaf(xr[r], wv[c], acc[r][c]);
    }
    __syncthreads();   // all layer-1 reads of xb/ws complete

    // h1 = leaky(acc + b1) -> xb (row-major), stage W2
    #pragma unroll
    for (int r = 0; r < 8; r++) {
        float h0 = leaky(acc[r][0] + bv1[0]);
        float h1v = leaky(acc[r][1] + bv1[1]);
        float h2v = leaky(acc[r][2] + bv1[2]);
        float h3 = leaky(acc[r][3] + bv1[3]);
        float h4 = leaky(acc[r][4] + bv1[4]);
        float h5 = leaky(acc[r][5] + bv1[5]);
        float h6 = leaky(acc[r][6] + bv1[6]);
        float h7 = leaky(acc[r][7] + bv1[7]);
        float4* dstp = (float4*)(xb + (ty * 8 + r) * D);
        dstp[tx * 2]     = make_float4(h0, h1v, h2v, h3);
        dstp[tx * 2 + 1] = make_float4(h4, h5, h6, h7);
    }
    const float4* W24 = (const float4*)W2;
    #pragma unroll
    for (int i = 0; i < 16; i++) {
        int idx = tid + i * 256;
        ((float4*)ws)[idx] = __ldg(W24 + idx);
    }
    __syncthreads();

    // ---- layer 2 ----
    #pragma unroll
    for (int r = 0; r < 8; r++)
        #pragma unroll
        for (int c = 0; c < 8; c++) acc[r][c] = 0.f;

    #pragma unroll 4
    for (int k = 0; k < D; k++) {
        float xr[8];
        #pragma unroll
        for (int r = 0; r < 8; r++) xr[r] = xb[(ty * 8 + r) * D + k];
        float4 wa = ((const float4*)(ws + k * D))[tx * 2];
        float4 wb = ((const float4*)(ws + k * D))[tx * 2 + 1];
        float wv[8] = {wa.x, wa.y, wa.z, wa.w, wb.x, wb.y, wb.z, wb.w};
        #pragma unroll
        for (int r = 0; r < 8; r++)
            #pragma unroll
            for (int c = 0; c < 8; c++) acc[r][c] = fmaf(xr[r], wv[c], acc[r][c]);
    }

    // ---- epilogue: h2 = leaky(acc + b2); out = h2 + feat; optionally h_out = h2 ----
    #pragma unroll
    for (int r = 0; r < 8; r++) {
        int grow = row0 + ty * 8 + r;
        if (grow >= N) continue;
        float h[8];
        #pragma unroll
        for (int c = 0; c < 8; c++) h[c] = leaky(acc[r][c] + bv2[c]);
        float4 f0 = __ldg(feat4 + (size_t)grow * 32 + tx * 2);
        float4 f1 = __ldg(feat4 + (size_t)grow * 32 + tx * 2 + 1);
        float4* o = (float4*)(out + (size_t)grow * D);
        o[tx * 2]     = make_float4(h[0] + f0.x, h[1] + f0.y, h[2] + f0.z, h[3] + f0.w);
        o[tx * 2 + 1] = make_float4(h[4] + f1.x, h[5] + f1.y, h[6] + f1.z, h[7] + f1.w);
        if (h_out) {
            float4* ho = (float4*)(h_out + (size_t)grow * D);
            ho[tx * 2]     = make_float4(h[0], h[1], h[2], h[3]);
            ho[tx * 2 + 1] = make_float4(h[4], h[5], h[6], h[7]);
        }
    }
}

extern "C" void kernel_launch(void* const* d_in, const int* in_sizes, int n_in,
                              void* d_out, int out_size) {
    const float* feat_row = (const float*)d_in[0];
    const float* feat_col = (const float*)d_in[1];
    const int*   src_c2r  = (const int*)d_in[2];
    const int*   dst_c2r  = (const int*)d_in[3];
    const float* w_c2r    = (const float*)d_in[4];
    const int*   src_r2c  = (const int*)d_in[5];
    const int*   dst_r2c  = (const int*)d_in[6];
    const float* w_r2c    = (const float*)d_in[7];
    const float* W1_c2r   = (const float*)d_in[8];
    const float* b1_c2r   = (const float*)d_in[9];
    const float* W2_c2r   = (const float*)d_in[10];
    const float* b2_c2r   = (const float*)d_in[11];
    const float* W1_r2c   = (const float*)d_in[12];
    const float* b1_r2c   = (const float*)d_in[13];
    const float* W2_r2c   = (const float*)d_in[14];
    const float* b2_r2c   = (const float*)d_in[15];
    const float* eps_c2r  = (const float*)d_in[16];
    const float* eps_r2c  = (const float*)d_in[17];

    const int E = in_sizes[2];

    float* out_row = (float*)d_out;
    float* out_col = out_row + (size_t)NROW * D;

    float *agg, *hrow;
    cudaGetSymbolAddress((void**)&agg,  g_agg);
    cudaGetSymbolAddress((void**)&hrow, g_hrow);

    const int smem = (BM * D + D * D) * (int)sizeof(float);   // 128 KB
    cudaFuncSetAttribute(mlp_kernel, cudaFuncAttributeMaxDynamicSharedMemorySize, smem);

    const int n4 = NROW * D / 4;
    const int zgrid = (n4 + 255) / 256;
    const int egrid = (int)(((long long)E * 32 + 255) / 256);
    const int g_row = (NROW + BM - 1) / BM;
    const int g_col = (NCOL + BM - 1) / BM;

    // col -> row
    zero_kernel<<<zgrid, 256>>>((float4*)agg, n4);
    agg_kernel<<<egrid, 256>>>((const float4*)feat_col, src_c2r, dst_c2r, w_c2r, agg, E);
    mlp_kernel<<<g_row, 256, smem>>>(feat_row, agg, W1_c2r, b1_c2r, W2_c2r, b2_c2r,
                                     eps_c2r, hrow, out_row, NROW);
    // row -> col (uses updated h_row)
    zero_kernel<<<zgrid, 256>>>((float4*)agg, n4);
    agg_kernel<<<egrid, 256>>>((const float4*)hrow, src_r2c, dst_r2c, w_r2c, agg, E);
    mlp_kernel<<<g_col, 256, smem>>>(feat_col, agg, W1_r2c, b1_r2c, W2_r2c, b2_r2c,
                                     eps_r2c, nullptr, out_col, NCOL);
}

// round 2
// speedup vs baseline: 1.5690x; 1.5690x over previous
#include <cuda_runtime.h>

#define D      128
#define NROW   50000
#define NCOL   50000
#define BM     128

// Scratch (alloc-free rule: __device__ globals)
__device__ float g_agg [(size_t)NROW * D];   // reused for both aggregation passes
__device__ float g_hrow[(size_t)NROW * D];   // h_row needed by second gather

__device__ __forceinline__ float leaky(float v) { return v >= 0.f ? v : 0.01f * v; }

__global__ void zero_kernel(float4* __restrict__ p, int n4) {
    int i = blockIdx.x * blockDim.x + threadIdx.x;
    if (i < n4) p[i] = make_float4(0.f, 0.f, 0.f, 0.f);
}

// One warp per edge; each lane handles one float4 (4 of 128 dims).
// Vectorized reduction: one red.global.add.v4.f32 per lane (4x fewer REDG lane-ops).
__global__ void agg_kernel(const float4* __restrict__ feat,
                           const int* __restrict__ src,
                           const int* __restrict__ dst,
                           const float* __restrict__ w,
                           float* __restrict__ agg, int E) {
    long long t = (long long)blockIdx.x * blockDim.x + threadIdx.x;
    int e = (int)(t >> 5);
    if (e >= E) return;
    int lane = (int)(t & 31);
    int s = __ldg(src + e);
    int d = __ldg(dst + e);
    float wt = __ldg(w + e);
    float4 v = __ldg(feat + (size_t)s * 32 + lane);
    float* a = agg + (size_t)d * D + lane * 4;
    asm volatile("red.global.add.v4.f32 [%0], {%1, %2, %3, %4};"
                 :: "l"(a), "f"(v.x * wt), "f"(v.y * wt), "f"(v.z * wt), "f"(v.w * wt)
                 : "memory");
}

// Fused 2-layer MLP + bias + LeakyReLU + residual.
// Block: 256 threads, BM=128 rows. Thread microtile 8 rows x 8 cols.
// smem: xb[BM*D] row-major activations, ws[D*D] current weight matrix.
__global__ void __launch_bounds__(256, 1)
mlp_kernel(const float* __restrict__ feat, const float* __restrict__ agg,
           const float* __restrict__ W1, const float* __restrict__ b1,
           const float* __restrict__ W2, const float* __restrict__ b2,
           const float* __restrict__ eps_p,
           float* __restrict__ h_out, float* __restrict__ out, int N) {
    extern __shared__ float sm[];
    float* xb = sm;            // BM*D floats (row-major)
    float* ws = sm + BM * D;   // D*D floats (row-major [k][j])

    const int tid = threadIdx.x;
    const int tx = tid & 15;      // 16 col-groups of 8
    const int ty = tid >> 4;      // 16 row-groups of 8
    const int row0 = blockIdx.x * BM;
    const float eps1 = 1.f + *eps_p;

    const float4* feat4 = (const float4*)feat;
    const float4* agg4  = (const float4*)agg;

    // ---- stage x = (1+eps)*feat + agg, and W1 ----
    #pragma unroll
    for (int i = 0; i < 16; i++) {
        int idx = tid + i * 256;           // 4096 float4 = BM*D floats
        int r   = idx >> 5;                // row in block
        int grow = row0 + r;
        float4 v = make_float4(0.f, 0.f, 0.f, 0.f);
        if (grow < N) {
            float4 f = __ldg(feat4 + (size_t)grow * 32 + (idx & 31));
            float4 a = __ldg(agg4  + (size_t)grow * 32 + (idx & 31));
            v.x = fmaf(eps1, f.x, a.x);
            v.y = fmaf(eps1, f.y, a.y);
            v.z = fmaf(eps1, f.z, a.z);
            v.w = fmaf(eps1, f.w, a.w);
        }
        ((float4*)xb)[idx] = v;
    }
    const float4* W14 = (const float4*)W1;
    #pragma unroll
    for (int i = 0; i < 16; i++) {
        int idx = tid + i * 256;
        ((float4*)ws)[idx] = __ldg(W14 + idx);
    }
    // biases into registers
    float bv1[8], bv2[8];
    {
        float4 a = ((const float4*)b1)[tx * 2], b = ((const float4*)b1)[tx * 2 + 1];
        bv1[0]=a.x; bv1[1]=a.y; bv1[2]=a.z; bv1[3]=a.w;
        bv1[4]=b.x; bv1[5]=b.y; bv1[6]=b.z; bv1[7]=b.w;
        float4 c = ((const float4*)b2)[tx * 2], d = ((const float4*)b2)[tx * 2 + 1];
        bv2[0]=c.x; bv2[1]=c.y; bv2[2]=c.z; bv2[3]=c.w;
        bv2[4]=d.x; bv2[5]=d.y; bv2[6]=d.z; bv2[7]=d.w;
    }
    __syncthreads();

    // ---- layer 1 ----
    float acc[8][8];
    #pragma unroll
    for (int r = 0; r < 8; r++)
        #pragma unroll
        for (int c = 0; c < 8; c++) acc[r][c] = 0.f;

    #pragma unroll 4
    for (int k = 0; k < D; k++) {
        float xr[8];
        #pragma unroll
        for (int r = 0; r < 8; r++) xr[r] = xb[(ty * 8 + r) * D + k];
        float4 wa = ((const float4*)(ws + k * D))[tx * 2];
        float4 wb = ((const float4*)(ws + k * D))[tx * 2 + 1];
        float wv[8] = {wa.x, wa.y, wa.z, wa.w, wb.x, wb.y, wb.z, wb.w};
        #pragma unroll
        for (int r = 0; r < 8; r++)
            #pragma unroll
            for (int c = 0; c < 8; c++) acc[r][c] = fmaf(xr[r], wv[c], acc[r][c]);
    }
    __syncthreads();   // all layer-1 reads of xb/ws complete

    // h1 = leaky(acc + b1) -> xb (row-major), stage W2
    #pragma unroll
    for (int r = 0; r < 8; r++) {
        float h0 = leaky(acc[r][0] + bv1[0]);
        float h1v = leaky(acc[r][1] + bv1[1]);
        float h2v = leaky(acc[r][2] + bv1[2]);
        float h3 = leaky(acc[r][3] + bv1[3]);
        float h4 = leaky(acc[r][4] + bv1[4]);
        float h5 = leaky(acc[r][5] + bv1[5]);
        float h6 = leaky(acc[r][6] + bv1[6]);
        float h7 = leaky(acc[r][7] + bv1[7]);
        float4* dstp = (float4*)(xb + (ty * 8 + r) * D);
        dstp[tx * 2]     = make_float4(h0, h1v, h2v, h3);
        dstp[tx * 2 + 1] = make_float4(h4, h5, h6, h7);
    }
    const float4* W24 = (const float4*)W2;
    #pragma unroll
    for (int i = 0; i < 16; i++) {
        int idx = tid + i * 256;
        ((float4*)ws)[idx] = __ldg(W24 + idx);
    }
    __syncthreads();

    // ---- layer 2 ----
    #pragma unroll
    for (int r = 0; r < 8; r++)
        #pragma unroll
        for (int c = 0; c < 8; c++) acc[r][c] = 0.f;

    #pragma unroll 4
    for (int k = 0; k < D; k++) {
        float xr[8];
        #pragma unroll
        for (int r = 0; r < 8; r++) xr[r] = xb[(ty * 8 + r) * D + k];
        float4 wa = ((const float4*)(ws + k * D))[tx * 2];
        float4 wb = ((const float4*)(ws + k * D))[tx * 2 + 1];
        float wv[8] = {wa.x, wa.y, wa.z, wa.w, wb.x, wb.y, wb.z, wb.w};
        #pragma unroll
        for (int r = 0; r < 8; r++)
            #pragma unroll
            for (int c = 0; c < 8; c++) acc[r][c] = fmaf(xr[r], wv[c], acc[r][c]);
    }

    // ---- epilogue: h2 = leaky(acc + b2); out = h2 + feat; optionally h_out = h2 ----
    #pragma unroll
    for (int r = 0; r < 8; r++) {
        int grow = row0 + ty * 8 + r;
        if (grow >= N) continue;
        float h[8];
        #pragma unroll
        for (int c = 0; c < 8; c++) h[c] = leaky(acc[r][c] + bv2[c]);
        float4 f0 = __ldg(feat4 + (size_t)grow * 32 + tx * 2);
        float4 f1 = __ldg(feat4 + (size_t)grow * 32 + tx * 2 + 1);
        float4* o = (float4*)(out + (size_t)grow * D);
        o[tx * 2]     = make_float4(h[0] + f0.x, h[1] + f0.y, h[2] + f0.z, h[3] + f0.w);
        o[tx * 2 + 1] = make_float4(h[4] + f1.x, h[5] + f1.y, h[6] + f1.z, h[7] + f1.w);
        if (h_out) {
            float4* ho = (float4*)(h_out + (size_t)grow * D);
            ho[tx * 2]     = make_float4(h[0], h[1], h[2], h[3]);
            ho[tx * 2 + 1] = make_float4(h[4], h[5], h[6], h[7]);
        }
    }
}

extern "C" void kernel_launch(void* const* d_in, const int* in_sizes, int n_in,
                              void* d_out, int out_size) {
    const float* feat_row = (const float*)d_in[0];
    const float* feat_col = (const float*)d_in[1];
    const int*   src_c2r  = (const int*)d_in[2];
    const int*   dst_c2r  = (const int*)d_in[3];
    const float* w_c2r    = (const float*)d_in[4];
    const int*   src_r2c  = (const int*)d_in[5];
    const int*   dst_r2c  = (const int*)d_in[6];
    const float* w_r2c    = (const float*)d_in[7];
    const float* W1_c2r   = (const float*)d_in[8];
    const float* b1_c2r   = (const float*)d_in[9];
    const float* W2_c2r   = (const float*)d_in[10];
    const float* b2_c2r   = (const float*)d_in[11];
    const float* W1_r2c   = (const float*)d_in[12];
    const float* b1_r2c   = (const float*)d_in[13];
    const float* W2_r2c   = (const float*)d_in[14];
    const float* b2_r2c   = (const float*)d_in[15];
    const float* eps_c2r  = (const float*)d_in[16];
    const float* eps_r2c  = (const float*)d_in[17];

    const int E = in_sizes[2];

    float* out_row = (float*)d_out;
    float* out_col = out_row + (size_t)NROW * D;

    float *agg, *hrow;
    cudaGetSymbolAddress((void**)&agg,  g_agg);
    cudaGetSymbolAddress((void**)&hrow, g_hrow);

    const int smem = (BM * D + D * D) * (int)sizeof(float);   // 128 KB
    cudaFuncSetAttribute(mlp_kernel, cudaFuncAttributeMaxDynamicSharedMemorySize, smem);

    const int n4 = NROW * D / 4;
    const int zgrid = (n4 + 255) / 256;
    const int egrid = (int)(((long long)E * 32 + 255) / 256);
    const int g_row = (NROW + BM - 1) / BM;
    const int g_col = (NCOL + BM - 1) / BM;

    // col -> row
    zero_kernel<<<zgrid, 256>>>((float4*)agg, n4);
    agg_kernel<<<egrid, 256>>>((const float4*)feat_col, src_c2r, dst_c2r, w_c2r, agg, E);
    mlp_kernel<<<g_row, 256, smem>>>(feat_row, agg, W1_c2r, b1_c2r, W2_c2r, b2_c2r,
                                     eps_c2r, hrow, out_row, NROW);
    // row -> col (uses updated h_row)
    zero_kernel<<<zgrid, 256>>>((float4*)agg, n4);
    agg_kernel<<<egrid, 256>>>((const float4*)hrow, src_r2c, dst_r2c, w_r2c, agg, E);
    mlp_kernel<<<g_col, 256, smem>>>(feat_col, agg, W1_r2c, b1_r2c, W2_r2c, b2_r2c,
                                     eps_r2c, nullptr, out_col, NCOL);
}

// round 4
// speedup vs baseline: 1.9534x; 1.2450x over previous
#include <cuda_runtime.h>
#include <cuda_bf16.h>
#include <cstdint>

#define D      128
#define NROW   50000
#define NCOL   50000
#define BM     128

// Scratch (alloc-free rule: __device__ globals)
__device__ float g_agg [(size_t)NROW * D];
__device__ float g_hrow[(size_t)NROW * D];

__device__ __forceinline__ float leaky(float v) { return v >= 0.f ? v : 0.01f * v; }

__global__ void zero_kernel(float4* __restrict__ p, int n4) {
    int i = blockIdx.x * blockDim.x + threadIdx.x;
    if (i < n4) p[i] = make_float4(0.f, 0.f, 0.f, 0.f);
}

// One warp per edge; one red.global.add.v4.f32 per lane.
__global__ void agg_kernel(const float4* __restrict__ feat,
                           const int* __restrict__ src,
                           const int* __restrict__ dst,
                           const float* __restrict__ w,
                           float* __restrict__ agg, int E) {
    long long t = (long long)blockIdx.x * blockDim.x + threadIdx.x;
    int e = (int)(t >> 5);
    if (e >= E) return;
    int lane = (int)(t & 31);
    int s = __ldg(src + e);
    int d = __ldg(dst + e);
    float wt = __ldg(w + e);
    float4 v = __ldg(feat + (size_t)s * 32 + lane);
    float* a = agg + (size_t)d * D + lane * 4;
    asm volatile("red.global.add.v4.f32 [%0], {%1, %2, %3, %4};"
                 :: "l"(a), "f"(v.x * wt), "f"(v.y * wt), "f"(v.z * wt), "f"(v.w * wt)
                 : "memory");
}

// ---------------- HMMA (mma.sync) MLP ----------------
// bf16 tiles: 128 rows x 128 k, row stride 136 bf16 (272B, conflict-free for ldmatrix)
#define LDB_B   272
#define TILE_B  (128 * LDB_B)       // 34816 bytes per bf16 tile
#define SM_XHI  0
#define SM_XLO  (SM_XHI + TILE_B)
#define SM_W1HI (SM_XLO + TILE_B)
#define SM_W1LO (SM_W1HI + TILE_B)
#define SM_W2HI (SM_W1LO + TILE_B)
#define SM_W2LO (SM_W2HI + TILE_B)
#define SM_B1   (SM_W2LO + TILE_B)       // 512B
#define SM_B2   (SM_B1 + 512)            // 512B
#define SM_TOTAL (SM_B2 + 512)           // 209920 bytes
// fp32 epilogue staging reuses the (dead) W1 region: 128 x 132 floats = 67584B
#define SM_FST  SM_W1HI
#define LDF     132

static __device__ __forceinline__ uint32_t smem_u32(const void* p) {
    uint32_t a;
    asm("{ .reg .u64 t; cvta.to.shared.u64 t, %1; cvt.u32.u64 %0, t; }" : "=r"(a) : "l"(p));
    return a;
}

static __device__ __forceinline__ void ldsm4(uint32_t* r, uint32_t addr) {
    asm volatile("ldmatrix.sync.aligned.m8n8.x4.shared.b16 {%0,%1,%2,%3}, [%4];"
                 : "=r"(r[0]), "=r"(r[1]), "=r"(r[2]), "=r"(r[3]) : "r"(addr));
}

static __device__ __forceinline__ void mma16816(float* d, const uint32_t* a,
                                                uint32_t b0, uint32_t b1) {
    asm volatile("mma.sync.aligned.m16n8k16.row.col.f32.bf16.bf16.f32 "
                 "{%0,%1,%2,%3}, {%4,%5,%6,%7}, {%8,%9}, {%0,%1,%2,%3};"
                 : "+f"(d[0]), "+f"(d[1]), "+f"(d[2]), "+f"(d[3])
                 : "r"(a[0]), "r"(a[1]), "r"(a[2]), "r"(a[3]), "r"(b0), "r"(b1));
}

// split 8 fp32 into bf16 hi/lo, packed pairwise into 4+4 u32 words
static __device__ __forceinline__ void split8(const float* x, uint32_t* hi, uint32_t* lo) {
    #pragma unroll
    for (int j = 0; j < 4; j++) {
        __nv_bfloat16 h0 = __float2bfloat16(x[2*j]);
        __nv_bfloat16 h1 = __float2bfloat16(x[2*j+1]);
        __nv_bfloat16 l0 = __float2bfloat16(x[2*j]   - __bfloat162float(h0));
        __nv_bfloat16 l1 = __float2bfloat16(x[2*j+1] - __bfloat162float(h1));
        hi[j] = (uint32_t)__bfloat16_as_ushort(h0) | ((uint32_t)__bfloat16_as_ushort(h1) << 16);
        lo[j] = (uint32_t)__bfloat16_as_ushort(l0) | ((uint32_t)__bfloat16_as_ushort(l1) << 16);
    }
}

// pack 2 fp32 into bf16x2 hi/lo words
static __device__ __forceinline__ void split2(float x0, float x1, uint32_t& hi, uint32_t& lo) {
    __nv_bfloat16 h0 = __float2bfloat16(x0);
    __nv_bfloat16 h1 = __float2bfloat16(x1);
    __nv_bfloat16 l0 = __float2bfloat16(x0 - __bfloat162float(h0));
    __nv_bfloat16 l1 = __float2bfloat16(x1 - __bfloat162float(h1));
    hi = (uint32_t)__bfloat16_as_ushort(h0) | ((uint32_t)__bfloat16_as_ushort(h1) << 16);
    lo = (uint32_t)__bfloat16_as_ushort(l0) | ((uint32_t)__bfloat16_as_ushort(l1) << 16);
}

// One layer: acc[16 n-tiles][4] += X(m0..m0+15, :) @ W^T, 3-way bf16 split.
static __device__ __forceinline__ void do_layer(uint32_t smb, uint32_t whi, uint32_t wlo,
                                                int m0, int lane, float acc[16][4]) {
    const int rsel = lane & 15;
    const uint32_t koff = (uint32_t)((lane >> 4) << 4);   // +16B for k+8 half
    #pragma unroll
    for (int kk = 0; kk < 8; kk++) {
        uint32_t rowk = (uint32_t)kk * 32 + koff;
        uint32_t ahi[4], alo[4];
        ldsm4(ahi, smb + SM_XHI + (uint32_t)(m0 + rsel) * LDB_B + rowk);
        ldsm4(alo, smb + SM_XLO + (uint32_t)(m0 + rsel) * LDB_B + rowk);
        #pragma unroll
        for (int p = 0; p < 8; p++) {
            uint32_t boff = (uint32_t)(p * 16 + rsel) * LDB_B + rowk;
            uint32_t bh[4], bl[4];
            ldsm4(bh, smb + whi + boff);
            ldsm4(bl, smb + wlo + boff);
            mma16816(acc[2*p],   ahi, bh[0], bh[2]);
            mma16816(acc[2*p],   ahi, bl[0], bl[2]);
            mma16816(acc[2*p],   alo, bh[0], bh[2]);
            mma16816(acc[2*p+1], ahi, bh[1], bh[3]);
            mma16816(acc[2*p+1], ahi, bl[1], bl[3]);
            mma16816(acc[2*p+1], alo, bh[1], bh[3]);
        }
    }
}

__global__ void __launch_bounds__(256, 1)
mlp_tc_kernel(const float* __restrict__ feat, const float* __restrict__ agg,
              const float* __restrict__ W1, const float* __restrict__ b1,
              const float* __restrict__ W2, const float* __restrict__ b2,
              const float* __restrict__ eps_p,
              float* __restrict__ h_out, float* __restrict__ out, int N) {
    extern __shared__ char sm[];
    const uint32_t smb = smem_u32(sm);
    const int tid = threadIdx.x;
    const int wid = tid >> 5;
    const int lane = tid & 31;
    const int m0 = wid * 16;
    const int row0 = blockIdx.x * BM;
    const float eps1 = 1.f + __ldg(eps_p);

    const float4* feat4 = (const float4*)feat;
    const float4* agg4  = (const float4*)agg;
    float* sB1 = (float*)(sm + SM_B1);
    float* sB2 = (float*)(sm + SM_B2);

    // ---- stage biases ----
    if (tid < 128) {
        sB1[tid] = __ldg(b1 + tid);
        sB2[tid] = __ldg(b2 + tid);
    }

    // ---- stage W1, W2 transposed (tile[n][k] = W[k][n]) as bf16 hi/lo ----
    #pragma unroll
    for (int m = 0; m < 2; m++) {
        const float* W = (m == 0) ? W1 : W2;
        const uint32_t HB = (m == 0) ? SM_W1HI : SM_W2HI;
        const uint32_t LB = (m == 0) ? SM_W1LO : SM_W2LO;
        #pragma unroll
        for (int i = 0; i < 8; i++) {
            int tt = tid + i * 256;            // 2048 tasks: n x kg
            int n = tt & 127, kg = tt >> 7;    // kg = k/8
            float v[8];
            #pragma unroll
            for (int j = 0; j < 8; j++) v[j] = __ldg(W + (kg * 8 + j) * D + n);
            uint32_t hi[4], lo[4];
            split8(v, hi, lo);
            uint32_t off = (uint32_t)n * LDB_B + (uint32_t)kg * 16;
            *(uint4*)(sm + HB + off) = make_uint4(hi[0], hi[1], hi[2], hi[3]);
            *(uint4*)(sm + LB + off) = make_uint4(lo[0], lo[1], lo[2], lo[3]);
        }
    }

    // ---- stage x = (1+eps)*feat + agg as bf16 hi/lo ----
    #pragma unroll
    for (int i = 0; i < 8; i++) {
        int tt = tid + i * 256;
        int tr = tt >> 4, kg = tt & 15;
        int grow = row0 + tr;
        float v[8];
        if (grow < N) {
            float4 f0 = __ldg(feat4 + (size_t)grow * 32 + kg * 2);
            float4 f1 = __ldg(feat4 + (size_t)grow * 32 + kg * 2 + 1);
            float4 a0 = __ldg(agg4  + (size_t)grow * 32 + kg * 2);
            float4 a1 = __ldg(agg4  + (size_t)grow * 32 + kg * 2 + 1);
            v[0] = fmaf(eps1, f0.x, a0.x); v[1] = fmaf(eps1, f0.y, a0.y);
            v[2] = fmaf(eps1, f0.z, a0.z); v[3] = fmaf(eps1, f0.w, a0.w);
            v[4] = fmaf(eps1, f1.x, a1.x); v[5] = fmaf(eps1, f1.y, a1.y);
            v[6] = fmaf(eps1, f1.z, a1.z); v[7] = fmaf(eps1, f1.w, a1.w);
        } else {
            #pragma unroll
            for (int j = 0; j < 8; j++) v[j] = 0.f;
        }
        uint32_t hi[4], lo[4];
        split8(v, hi, lo);
        uint32_t off = (uint32_t)tr * LDB_B + (uint32_t)kg * 16;
        *(uint4*)(sm + SM_XHI + off) = make_uint4(hi[0], hi[1], hi[2], hi[3]);
        *(uint4*)(sm + SM_XLO + off) = make_uint4(lo[0], lo[1], lo[2], lo[3]);
    }
    __syncthreads();

    // ---- layer 1 ----
    float acc[16][4];
    #pragma unroll
    for (int t = 0; t < 16; t++)
        #pragma unroll
        for (int j = 0; j < 4; j++) acc[t][j] = 0.f;
    do_layer(smb, SM_W1HI, SM_W1LO, m0, lane, acc);

    // writeback h1 = leaky(acc + b1) into X tiles (rows are warp-exclusive)
    {
        const int r0 = m0 + (lane >> 2);
        const int c0 = 2 * (lane & 3);
        #pragma unroll
        for (int nt = 0; nt < 16; nt++) {
            int c = nt * 8 + c0;
            float v0 = leaky(acc[nt][0] + sB1[c]);
            float v1 = leaky(acc[nt][1] + sB1[c + 1]);
            float v2 = leaky(acc[nt][2] + sB1[c]);
            float v3 = leaky(acc[nt][3] + sB1[c + 1]);
            uint32_t h01, l01, h23, l23;
            split2(v0, v1, h01, l01);
            split2(v2, v3, h23, l23);
            uint32_t o0 = (uint32_t)r0 * LDB_B + (uint32_t)c * 2;
            uint32_t o1 = o0 + 8u * LDB_B;
            *(uint32_t*)(sm + SM_XHI + o0) = h01;
            *(uint32_t*)(sm + SM_XLO + o0) = l01;
            *(uint32_t*)(sm + SM_XHI + o1) = h23;
            *(uint32_t*)(sm + SM_XLO + o1) = l23;
        }
    }
    __syncwarp();

    // ---- layer 2 ----
    #pragma unroll
    for (int t = 0; t < 16; t++)
        #pragma unroll
        for (int j = 0; j < 4; j++) acc[t][j] = 0.f;
    do_layer(smb, SM_W2HI, SM_W2LO, m0, lane, acc);

    // ---- epilogue: stage h2 = leaky(acc + b2) as fp32 (reuse W1 region) ----
    __syncthreads();   // everyone done reading W1 before clobbering it
    {
        float* fst = (float*)(sm + SM_FST);
        const int r0 = m0 + (lane >> 2);
        const int c0 = 2 * (lane & 3);
        #pragma unroll
        for (int nt = 0; nt < 16; nt++) {
            int c = nt * 8 + c0;
            float v0 = leaky(acc[nt][0] + sB2[c]);
            float v1 = leaky(acc[nt][1] + sB2[c + 1]);
            float v2 = leaky(acc[nt][2] + sB2[c]);
            float v3 = leaky(acc[nt][3] + sB2[c + 1]);
            *(float2*)(fst + (size_t)r0 * LDF + c)       = make_float2(v0, v1);
            *(float2*)(fst + (size_t)(r0 + 8) * LDF + c) = make_float2(v2, v3);
        }
    }
    __syncthreads();

    // coalesced final writes: out = h2 + feat; h_out = h2
    {
        const float* fst = (const float*)(sm + SM_FST);
        #pragma unroll
        for (int i = 0; i < 16; i++) {
            int idx = tid + i * 256;          // 4096 float4 tasks
            int r = idx >> 5, c4 = idx & 31;
            int grow = row0 + r;
            if (grow >= N) continue;
            const float* p = fst + (size_t)r * LDF + c4 * 4;
            float4 h = make_float4(p[0], p[1], p[2], p[3]);
            float4 fv = __ldg(feat4 + (size_t)grow * 32 + c4);
            ((float4*)out)[(size_t)grow * 32 + c4] =
                make_float4(h.x + fv.x, h.y + fv.y, h.z + fv.z, h.w + fv.w);
            if (h_out)
                ((float4*)h_out)[(size_t)grow * 32 + c4] = h;
        }
    }
}

extern "C" void kernel_launch(void* const* d_in, const int* in_sizes, int n_in,
                              void* d_out, int out_size) {
    const float* feat_row = (const float*)d_in[0];
    const float* feat_col = (const float*)d_in[1];
    const int*   src_c2r  = (const int*)d_in[2];
    const int*   dst_c2r  = (const int*)d_in[3];
    const float* w_c2r    = (const float*)d_in[4];
    const int*   src_r2c  = (const int*)d_in[5];
    const int*   dst_r2c  = (const int*)d_in[6];
    const float* w_r2c    = (const float*)d_in[7];
    const float* W1_c2r   = (const float*)d_in[8];
    const float* b1_c2r   = (const float*)d_in[9];
    const float* W2_c2r   = (const float*)d_in[10];
    const float* b2_c2r   = (const float*)d_in[11];
    const float* W1_r2c   = (const float*)d_in[12];
    const float* b1_r2c   = (const float*)d_in[13];
    const float* W2_r2c   = (const float*)d_in[14];
    const float* b2_r2c   = (const float*)d_in[15];
    const float* eps_c2r  = (const float*)d_in[16];
    const float* eps_r2c  = (const float*)d_in[17];

    const int E = in_sizes[2];

    float* out_row = (float*)d_out;
    float* out_col = out_row + (size_t)NROW * D;

    float *agg, *hrow;
    cudaGetSymbolAddress((void**)&agg,  g_agg);
    cudaGetSymbolAddress((void**)&hrow, g_hrow);

    cudaFuncSetAttribute(mlp_tc_kernel, cudaFuncAttributeMaxDynamicSharedMemorySize, SM_TOTAL);

    const int n4 = NROW * D / 4;
    const int zgrid = (n4 + 255) / 256;
    const int egrid = (int)(((long long)E * 32 + 255) / 256);
    const int g_row = (NROW + BM - 1) / BM;
    const int g_col = (NCOL + BM - 1) / BM;

    // col -> row
    zero_kernel<<<zgrid, 256>>>((float4*)agg, n4);
    agg_kernel<<<egrid, 256>>>((const float4*)feat_col, src_c2r, dst_c2r, w_c2r, agg, E);
    mlp_tc_kernel<<<g_row, 256, SM_TOTAL>>>(feat_row, agg, W1_c2r, b1_c2r, W2_c2r, b2_c2r,
                                            eps_c2r, hrow, out_row, NROW);
    // row -> col (uses updated h_row)
    zero_kernel<<<zgrid, 256>>>((float4*)agg, n4);
    agg_kernel<<<egrid, 256>>>((const float4*)hrow, src_r2c, dst_r2c, w_r2c, agg, E);
    mlp_tc_kernel<<<g_col, 256, SM_TOTAL>>>(feat_col, agg, W1_r2c, b1_r2c, W2_r2c, b2_r2c,
                                            eps_r2c, nullptr, out_col, NCOL);
}

// round 5
// speedup vs baseline: 1.9638x; 1.0053x over previous
#include <cuda_runtime.h>
#include <cuda_bf16.h>
#include <cstdint>

#define D      128
#define NROW   50000
#define NCOL   50000
#define BM     128

// Scratch (alloc-free rule: __device__ globals)
__device__ float g_agg1[(size_t)NROW * D];
__device__ float g_agg2[(size_t)NCOL * D];
__device__ float g_hrow[(size_t)NROW * D];

__device__ __forceinline__ float leaky(float v) { return v >= 0.f ? v : 0.01f * v; }

__global__ void zero_kernel(float4* __restrict__ p, int n4) {
    int i = blockIdx.x * blockDim.x + threadIdx.x;
    if (i < n4) p[i] = make_float4(0.f, 0.f, 0.f, 0.f);
}

// One warp per edge; one red.global.add.v4.f32 per lane.
__global__ void agg_kernel(const float4* __restrict__ feat,
                           const int* __restrict__ src,
                           const int* __restrict__ dst,
                           const float* __restrict__ w,
                           float* __restrict__ agg, int E) {
    long long t = (long long)blockIdx.x * blockDim.x + threadIdx.x;
    int e = (int)(t >> 5);
    if (e >= E) return;
    int lane = (int)(t & 31);
    int s = __ldg(src + e);
    int d = __ldg(dst + e);
    float wt = __ldg(w + e);
    float4 v = __ldg(feat + (size_t)s * 32 + lane);
    float* a = agg + (size_t)d * D + lane * 4;
    asm volatile("red.global.add.v4.f32 [%0], {%1, %2, %3, %4};"
                 :: "l"(a), "f"(v.x * wt), "f"(v.y * wt), "f"(v.z * wt), "f"(v.w * wt)
                 : "memory");
}

// ---------------- HMMA (mma.sync) MLP ----------------
// bf16 tiles: 128 rows x 128 k, row stride 136 bf16 (272B)
#define LDB_B   272
#define TILE_B  (128 * LDB_B)
#define SM_XHI  0
#define SM_XLO  (SM_XHI + TILE_B)
#define SM_W1HI (SM_XLO + TILE_B)
#define SM_W1LO (SM_W1HI + TILE_B)
#define SM_W2HI (SM_W1LO + TILE_B)
#define SM_W2LO (SM_W2HI + TILE_B)
#define SM_B1   (SM_W2LO + TILE_B)
#define SM_B2   (SM_B1 + 512)
#define SM_TOTAL (SM_B2 + 512)           // 209920 bytes
// fp32 epilogue staging reuses the (dead) W1 region: 128 x 132 floats
#define SM_FST  SM_W1HI
#define LDF     132

static __device__ __forceinline__ uint32_t smem_u32(const void* p) {
    uint32_t a;
    asm("{ .reg .u64 t; cvta.to.shared.u64 t, %1; cvt.u32.u64 %0, t; }" : "=r"(a) : "l"(p));
    return a;
}

static __device__ __forceinline__ void ldsm4(uint32_t* r, uint32_t addr) {
    asm volatile("ldmatrix.sync.aligned.m8n8.x4.shared.b16 {%0,%1,%2,%3}, [%4];"
                 : "=r"(r[0]), "=r"(r[1]), "=r"(r[2]), "=r"(r[3]) : "r"(addr));
}

static __device__ __forceinline__ void mma16816(float* d, const uint32_t* a,
                                                uint32_t b0, uint32_t b1) {
    asm volatile("mma.sync.aligned.m16n8k16.row.col.f32.bf16.bf16.f32 "
                 "{%0,%1,%2,%3}, {%4,%5,%6,%7}, {%8,%9}, {%0,%1,%2,%3};"
                 : "+f"(d[0]), "+f"(d[1]), "+f"(d[2]), "+f"(d[3])
                 : "r"(a[0]), "r"(a[1]), "r"(a[2]), "r"(a[3]), "r"(b0), "r"(b1));
}

static __device__ __forceinline__ void split8(const float* x, uint32_t* hi, uint32_t* lo) {
    #pragma unroll
    for (int j = 0; j < 4; j++) {
        __nv_bfloat16 h0 = __float2bfloat16(x[2*j]);
        __nv_bfloat16 h1 = __float2bfloat16(x[2*j+1]);
        __nv_bfloat16 l0 = __float2bfloat16(x[2*j]   - __bfloat162float(h0));
        __nv_bfloat16 l1 = __float2bfloat16(x[2*j+1] - __bfloat162float(h1));
        hi[j] = (uint32_t)__bfloat16_as_ushort(h0) | ((uint32_t)__bfloat16_as_ushort(h1) << 16);
        lo[j] = (uint32_t)__bfloat16_as_ushort(l0) | ((uint32_t)__bfloat16_as_ushort(l1) << 16);
    }
}

static __device__ __forceinline__ void split2(float x0, float x1, uint32_t& hi, uint32_t& lo) {
    __nv_bfloat16 h0 = __float2bfloat16(x0);
    __nv_bfloat16 h1 = __float2bfloat16(x1);
    __nv_bfloat16 l0 = __float2bfloat16(x0 - __bfloat162float(h0));
    __nv_bfloat16 l1 = __float2bfloat16(x1 - __bfloat162float(h1));
    hi = (uint32_t)__bfloat16_as_ushort(h0) | ((uint32_t)__bfloat16_as_ushort(h1) << 16);
    lo = (uint32_t)__bfloat16_as_ushort(l0) | ((uint32_t)__bfloat16_as_ushort(l1) << 16);
}

// One layer for one warp: acc[8][4] += X(m0..m0+15, :) @ W^T over n-range
// [wn*64, wn*64+64). 3-way bf16 split, accumulators interleaved so consecutive
// MMAs never share an accumulator at distance < 2.
static __device__ __forceinline__ void do_layer(uint32_t smb, uint32_t whi, uint32_t wlo,
                                                int m0, int wn, int lane, float acc[8][4]) {
    const int rsel = lane & 15;
    const uint32_t koff = (uint32_t)((lane >> 4) << 4);
    #pragma unroll
    for (int kk = 0; kk < 8; kk++) {
        uint32_t rowk = (uint32_t)kk * 32 + koff;
        uint32_t ahi[4], alo[4];
        ldsm4(ahi, smb + SM_XHI + (uint32_t)(m0 + rsel) * LDB_B + rowk);
        ldsm4(alo, smb + SM_XLO + (uint32_t)(m0 + rsel) * LDB_B + rowk);
        #pragma unroll
        for (int p = 0; p < 4; p++) {
            uint32_t boff = (uint32_t)((wn * 4 + p) * 16 + rsel) * LDB_B + rowk;
            uint32_t bh[4], bl[4];
            ldsm4(bh, smb + whi + boff);
            ldsm4(bl, smb + wlo + boff);
            mma16816(acc[2*p],   ahi, bh[0], bh[2]);
            mma16816(acc[2*p+1], ahi, bh[1], bh[3]);
            mma16816(acc[2*p],   ahi, bl[0], bl[2]);
            mma16816(acc[2*p+1], ahi, bl[1], bl[3]);
            mma16816(acc[2*p],   alo, bh[0], bh[2]);
            mma16816(acc[2*p+1], alo, bh[1], bh[3]);
        }
    }
}

__global__ void __launch_bounds__(512, 1)
mlp_tc_kernel(const float* __restrict__ feat, const float* __restrict__ agg,
              const float* __restrict__ W1, const float* __restrict__ b1,
              const float* __restrict__ W2, const float* __restrict__ b2,
              const float* __restrict__ eps_p,
              float* __restrict__ h_out, float* __restrict__ out, int N) {
    extern __shared__ char sm[];
    const uint32_t smb = smem_u32(sm);
    const int tid = threadIdx.x;
    const int wid = tid >> 5;
    const int lane = tid & 31;
    const int m0 = (wid & 7) * 16;     // 8 m-tiles of 16 rows
    const int wn = wid >> 3;           // 2 n-halves of 64 cols
    const int row0 = blockIdx.x * BM;
    const float eps1 = 1.f + __ldg(eps_p);

    const float4* feat4 = (const float4*)feat;
    const float4* agg4  = (const float4*)agg;
    float* sB1 = (float*)(sm + SM_B1);
    float* sB2 = (float*)(sm + SM_B2);

    if (tid < 128) {
        sB1[tid] = __ldg(b1 + tid);
        sB2[tid] = __ldg(b2 + tid);
    }

    // ---- stage W1, W2 transposed (tile[n][k] = W[k][n]) as bf16 hi/lo ----
    #pragma unroll
    for (int m = 0; m < 2; m++) {
        const float* W = (m == 0) ? W1 : W2;
        const uint32_t HB = (m == 0) ? SM_W1HI : SM_W2HI;
        const uint32_t LB = (m == 0) ? SM_W1LO : SM_W2LO;
        #pragma unroll
        for (int i = 0; i < 4; i++) {
            int tt = tid + i * 512;            // 2048 tasks: n x kg
            int n = tt & 127, kg = tt >> 7;
            float v[8];
            #pragma unroll
            for (int j = 0; j < 8; j++) v[j] = __ldg(W + (kg * 8 + j) * D + n);
            uint32_t hi[4], lo[4];
            split8(v, hi, lo);
            uint32_t off = (uint32_t)n * LDB_B + (uint32_t)kg * 16;
            *(uint4*)(sm + HB + off) = make_uint4(hi[0], hi[1], hi[2], hi[3]);
            *(uint4*)(sm + LB + off) = make_uint4(lo[0], lo[1], lo[2], lo[3]);
        }
    }

    // ---- stage x = (1+eps)*feat + agg as bf16 hi/lo ----
    #pragma unroll
    for (int i = 0; i < 4; i++) {
        int tt = tid + i * 512;
        int tr = tt >> 4, kg = tt & 15;
        int grow = row0 + tr;
        float v[8];
        if (grow < N) {
            float4 f0 = __ldg(feat4 + (size_t)grow * 32 + kg * 2);
            float4 f1 = __ldg(feat4 + (size_t)grow * 32 + kg * 2 + 1);
            float4 a0 = __ldg(agg4  + (size_t)grow * 32 + kg * 2);
            float4 a1 = __ldg(agg4  + (size_t)grow * 32 + kg * 2 + 1);
            v[0] = fmaf(eps1, f0.x, a0.x); v[1] = fmaf(eps1, f0.y, a0.y);
            v[2] = fmaf(eps1, f0.z, a0.z); v[3] = fmaf(eps1, f0.w, a0.w);
            v[4] = fmaf(eps1, f1.x, a1.x); v[5] = fmaf(eps1, f1.y, a1.y);
            v[6] = fmaf(eps1, f1.z, a1.z); v[7] = fmaf(eps1, f1.w, a1.w);
        } else {
            #pragma unroll
            for (int j = 0; j < 8; j++) v[j] = 0.f;
        }
        uint32_t hi[4], lo[4];
        split8(v, hi, lo);
        uint32_t off = (uint32_t)tr * LDB_B + (uint32_t)kg * 16;
        *(uint4*)(sm + SM_XHI + off) = make_uint4(hi[0], hi[1], hi[2], hi[3]);
        *(uint4*)(sm + SM_XLO + off) = make_uint4(lo[0], lo[1], lo[2], lo[3]);
    }
    __syncthreads();

    // ---- layer 1 ----
    float acc[8][4];
    #pragma unroll
    for (int t = 0; t < 8; t++)
        #pragma unroll
        for (int j = 0; j < 4; j++) acc[t][j] = 0.f;
    do_layer(smb, SM_W1HI, SM_W1LO, m0, wn, lane, acc);
    __syncthreads();   // all layer-1 reads of X done before overwrite

    // writeback h1 = leaky(acc + b1) into X tiles
    {
        const int r0 = m0 + (lane >> 2);
        const int c0 = 2 * (lane & 3);
        #pragma unroll
        for (int p = 0; p < 4; p++) {
            #pragma unroll
            for (int s = 0; s < 2; s++) {
                int c = (wn * 4 + p) * 16 + s * 8 + c0;
                float v0 = leaky(acc[2*p+s][0] + sB1[c]);
                float v1 = leaky(acc[2*p+s][1] + sB1[c + 1]);
                float v2 = leaky(acc[2*p+s][2] + sB1[c]);
                float v3 = leaky(acc[2*p+s][3] + sB1[c + 1]);
                uint32_t h01, l01, h23, l23;
                split2(v0, v1, h01, l01);
                split2(v2, v3, h23, l23);
                uint32_t o0 = (uint32_t)r0 * LDB_B + (uint32_t)c * 2;
                uint32_t o1 = o0 + 8u * LDB_B;
                *(uint32_t*)(sm + SM_XHI + o0) = h01;
                *(uint32_t*)(sm + SM_XLO + o0) = l01;
                *(uint32_t*)(sm + SM_XHI + o1) = h23;
                *(uint32_t*)(sm + SM_XLO + o1) = l23;
            }
        }
    }
    __syncthreads();

    // ---- layer 2 ----
    #pragma unroll
    for (int t = 0; t < 8; t++)
        #pragma unroll
        for (int j = 0; j < 4; j++) acc[t][j] = 0.f;
    do_layer(smb, SM_W2HI, SM_W2LO, m0, wn, lane, acc);

    // ---- epilogue: stage h2 = leaky(acc + b2) as fp32 (reuse W1 region) ----
    __syncthreads();
    {
        float* fst = (float*)(sm + SM_FST);
        const int r0 = m0 + (lane >> 2);
        const int c0 = 2 * (lane & 3);
        #pragma unroll
        for (int p = 0; p < 4; p++) {
            #pragma unroll
            for (int s = 0; s < 2; s++) {
                int c = (wn * 4 + p) * 16 + s * 8 + c0;
                float v0 = leaky(acc[2*p+s][0] + sB2[c]);
                float v1 = leaky(acc[2*p+s][1] + sB2[c + 1]);
                float v2 = leaky(acc[2*p+s][2] + sB2[c]);
                float v3 = leaky(acc[2*p+s][3] + sB2[c + 1]);
                *(float2*)(fst + (size_t)r0 * LDF + c)       = make_float2(v0, v1);
                *(float2*)(fst + (size_t)(r0 + 8) * LDF + c) = make_float2(v2, v3);
            }
        }
    }
    __syncthreads();

    // coalesced final writes: out = h2 + feat; h_out = h2
    {
        const float* fst = (const float*)(sm + SM_FST);
        #pragma unroll
        for (int i = 0; i < 8; i++) {
            int idx = tid + i * 512;          // 4096 float4 tasks
            int r = idx >> 5, c4 = idx & 31;
            int grow = row0 + r;
            if (grow >= N) continue;
            const float* p = fst + (size_t)r * LDF + c4 * 4;
            float4 h = make_float4(p[0], p[1], p[2], p[3]);
            float4 fv = __ldg(feat4 + (size_t)grow * 32 + c4);
            ((float4*)out)[(size_t)grow * 32 + c4] =
                make_float4(h.x + fv.x, h.y + fv.y, h.z + fv.z, h.w + fv.w);
            if (h_out)
                ((float4*)h_out)[(size_t)grow * 32 + c4] = h;
        }
    }
}

extern "C" void kernel_launch(void* const* d_in, const int* in_sizes, int n_in,
                              void* d_out, int out_size) {
    const float* feat_row = (const float*)d_in[0];
    const float* feat_col = (const float*)d_in[1];
    const int*   src_c2r  = (const int*)d_in[2];
    const int*   dst_c2r  = (const int*)d_in[3];
    const float* w_c2r    = (const float*)d_in[4];
    const int*   src_r2c  = (const int*)d_in[5];
    const int*   dst_r2c  = (const int*)d_in[6];
    const float* w_r2c    = (const float*)d_in[7];
    const float* W1_c2r   = (const float*)d_in[8];
    const float* b1_c2r   = (const float*)d_in[9];
    const float* W2_c2r   = (const float*)d_in[10];
    const float* b2_c2r   = (const float*)d_in[11];
    const float* W1_r2c   = (const float*)d_in[12];
    const float* b1_r2c   = (const float*)d_in[13];
    const float* W2_r2c   = (const float*)d_in[14];
    const float* b2_r2c   = (const float*)d_in[15];
    const float* eps_c2r  = (const float*)d_in[16];
    const float* eps_r2c  = (const float*)d_in[17];

    const int E = in_sizes[2];

    float* out_row = (float*)d_out;
    float* out_col = out_row + (size_t)NROW * D;

    float *agg1, *agg2, *hrow;
    cudaGetSymbolAddress((void**)&agg1, g_agg1);
    cudaGetSymbolAddress((void**)&agg2, g_agg2);
    cudaGetSymbolAddress((void**)&hrow, g_hrow);

    cudaFuncSetAttribute(mlp_tc_kernel, cudaFuncAttributeMaxDynamicSharedMemorySize, SM_TOTAL);

    const int n4 = NROW * D / 4;          // agg1 and agg2 are contiguous? (separate symbols; zero each)
    const int zgrid = (n4 + 255) / 256;
    const int egrid = (int)(((long long)E * 32 + 255) / 256);
    const int g_row = (NROW + BM - 1) / BM;
    const int g_col = (NCOL + BM - 1) / BM;

    // zero both agg buffers up front
    zero_kernel<<<zgrid, 256>>>((float4*)agg1, n4);
    zero_kernel<<<zgrid, 256>>>((float4*)agg2, n4);
    // col -> row
    agg_kernel<<<egrid, 256>>>((const float4*)feat_col, src_c2r, dst_c2r, w_c2r, agg1, E);
    mlp_tc_kernel<<<g_row, 512, SM_TOTAL>>>(feat_row, agg1, W1_c2r, b1_c2r, W2_c2r, b2_c2r,
                                            eps_c2r, hrow, out_row, NROW);
    // row -> col (uses updated h_row)
    agg_kernel<<<egrid, 256>>>((const float4*)hrow, src_r2c, dst_r2c, w_r2c, agg2, E);
    mlp_tc_kernel<<<g_col, 512, SM_TOTAL>>>(feat_col, agg2, W1_r2c, b1_r2c, W2_r2c, b2_r2c,
                                            eps_r2c, nullptr, out_col, NCOL);
}

// round 6
// speedup vs baseline: 1.9968x; 1.0168x over previous
#include <cuda_runtime.h>
#include <cuda_bf16.h>
#include <cstdint>

#define D      128
#define NROW   50000
#define NCOL   50000
#define BM     64

// Scratch (alloc-free rule: __device__ globals)
__device__ float g_agg1[(size_t)NROW * D];
__device__ float g_agg2[(size_t)NCOL * D];
__device__ float g_hrow[(size_t)NROW * D];

__device__ __forceinline__ float leaky(float v) { return v >= 0.f ? v : 0.01f * v; }

__global__ void zero_kernel(float4* __restrict__ p, int n4) {
    int i = blockIdx.x * blockDim.x + threadIdx.x;
    if (i < n4) p[i] = make_float4(0.f, 0.f, 0.f, 0.f);
}

// One warp per edge; one red.global.add.v4.f32 per lane.
__global__ void agg_kernel(const float4* __restrict__ feat,
                           const int* __restrict__ src,
                           const int* __restrict__ dst,
                           const float* __restrict__ w,
                           float* __restrict__ agg, int E) {
    long long t = (long long)blockIdx.x * blockDim.x + threadIdx.x;
    int e = (int)(t >> 5);
    if (e >= E) return;
    int lane = (int)(t & 31);
    int s = __ldg(src + e);
    int d = __ldg(dst + e);
    float wt = __ldg(w + e);
    float4 v = __ldg(feat + (size_t)s * 32 + lane);
    float* a = agg + (size_t)d * D + lane * 4;
    asm volatile("red.global.add.v4.f32 [%0], {%1, %2, %3, %4};"
                 :: "l"(a), "f"(v.x * wt), "f"(v.y * wt), "f"(v.z * wt), "f"(v.w * wt)
                 : "memory");
}

// ---------------- HMMA (mma.sync) MLP ----------------
// bf16 tiles, row stride 272B (conflict-spread for ldmatrix).
// X tiles: 64 rows; W tile: 128 n-rows (ONE layer at a time, restaged).
#define LDB_B   272
#define XTILE_B (64 * LDB_B)         // 17408
#define WTILE_B (128 * LDB_B)        // 34816
#define SM_XHI  0
#define SM_XLO  (SM_XHI + XTILE_B)
#define SM_WHI  (SM_XLO + XTILE_B)
#define SM_WLO  (SM_WHI + WTILE_B)
#define SM_B1   (SM_WLO + WTILE_B)
#define SM_B2   (SM_B1 + 512)
#define SM_TOTAL (SM_B2 + 512)        // 105472 bytes -> 2 CTAs/SM
// fp32 epilogue staging reuses the (dead) WHI region: 64 x 132 floats = 33792B
#define SM_FST  SM_WHI
#define LDF     132

static __device__ __forceinline__ uint32_t smem_u32(const void* p) {
    uint32_t a;
    asm("{ .reg .u64 t; cvta.to.shared.u64 t, %1; cvt.u32.u64 %0, t; }" : "=r"(a) : "l"(p));
    return a;
}

static __device__ __forceinline__ void ldsm4(uint32_t* r, uint32_t addr) {
    asm volatile("ldmatrix.sync.aligned.m8n8.x4.shared.b16 {%0,%1,%2,%3}, [%4];"
                 : "=r"(r[0]), "=r"(r[1]), "=r"(r[2]), "=r"(r[3]) : "r"(addr));
}

static __device__ __forceinline__ void mma16816(float* d, const uint32_t* a,
                                                uint32_t b0, uint32_t b1) {
    asm volatile("mma.sync.aligned.m16n8k16.row.col.f32.bf16.bf16.f32 "
                 "{%0,%1,%2,%3}, {%4,%5,%6,%7}, {%8,%9}, {%0,%1,%2,%3};"
                 : "+f"(d[0]), "+f"(d[1]), "+f"(d[2]), "+f"(d[3])
                 : "r"(a[0]), "r"(a[1]), "r"(a[2]), "r"(a[3]), "r"(b0), "r"(b1));
}

static __device__ __forceinline__ void split8(const float* x, uint32_t* hi, uint32_t* lo) {
    #pragma unroll
    for (int j = 0; j < 4; j++) {
        __nv_bfloat16 h0 = __float2bfloat16(x[2*j]);
        __nv_bfloat16 h1 = __float2bfloat16(x[2*j+1]);
        __nv_bfloat16 l0 = __float2bfloat16(x[2*j]   - __bfloat162float(h0));
        __nv_bfloat16 l1 = __float2bfloat16(x[2*j+1] - __bfloat162float(h1));
        hi[j] = (uint32_t)__bfloat16_as_ushort(h0) | ((uint32_t)__bfloat16_as_ushort(h1) << 16);
        lo[j] = (uint32_t)__bfloat16_as_ushort(l0) | ((uint32_t)__bfloat16_as_ushort(l1) << 16);
    }
}

static __device__ __forceinline__ void split2(float x0, float x1, uint32_t& hi, uint32_t& lo) {
    __nv_bfloat16 h0 = __float2bfloat16(x0);
    __nv_bfloat16 h1 = __float2bfloat16(x1);
    __nv_bfloat16 l0 = __float2bfloat16(x0 - __bfloat162float(h0));
    __nv_bfloat16 l1 = __float2bfloat16(x1 - __bfloat162float(h1));
    hi = (uint32_t)__bfloat16_as_ushort(h0) | ((uint32_t)__bfloat16_as_ushort(h1) << 16);
    lo = (uint32_t)__bfloat16_as_ushort(l0) | ((uint32_t)__bfloat16_as_ushort(l1) << 16);
}

// stage one weight matrix (transposed, bf16 hi/lo) into SM_WHI/SM_WLO
static __device__ __forceinline__ void stage_w(char* sm, const float* __restrict__ W, int tid) {
    #pragma unroll
    for (int i = 0; i < 8; i++) {
        int tt = tid + i * 256;            // 2048 tasks: n x kg
        int n = tt & 127, kg = tt >> 7;
        float v[8];
        #pragma unroll
        for (int j = 0; j < 8; j++) v[j] = __ldg(W + (kg * 8 + j) * D + n);
        uint32_t hi[4], lo[4];
        split8(v, hi, lo);
        uint32_t off = (uint32_t)n * LDB_B + (uint32_t)kg * 16;
        *(uint4*)(sm + SM_WHI + off) = make_uint4(hi[0], hi[1], hi[2], hi[3]);
        *(uint4*)(sm + SM_WLO + off) = make_uint4(lo[0], lo[1], lo[2], lo[3]);
    }
}

// One layer for one warp: acc[8][4] += X(m0..m0+15, :) @ W^T over n-cols
// [wn*64, wn*64+64). 3-way bf16 split, interleaved accumulators.
static __device__ __forceinline__ void do_layer(uint32_t smb, int m0, int wn, int lane,
                                                float acc[8][4]) {
    const int rsel = lane & 15;
    const uint32_t koff = (uint32_t)((lane >> 4) << 4);
    #pragma unroll
    for (int kk = 0; kk < 8; kk++) {
        uint32_t rowk = (uint32_t)kk * 32 + koff;
        uint32_t ahi[4], alo[4];
        ldsm4(ahi, smb + SM_XHI + (uint32_t)(m0 + rsel) * LDB_B + rowk);
        ldsm4(alo, smb + SM_XLO + (uint32_t)(m0 + rsel) * LDB_B + rowk);
        #pragma unroll
        for (int p = 0; p < 4; p++) {
            uint32_t boff = (uint32_t)((wn * 4 + p) * 16 + rsel) * LDB_B + rowk;
            uint32_t bh[4], bl[4];
            ldsm4(bh, smb + SM_WHI + boff);
            ldsm4(bl, smb + SM_WLO + boff);
            mma16816(acc[2*p],   ahi, bh[0], bh[2]);
            mma16816(acc[2*p+1], ahi, bh[1], bh[3]);
            mma16816(acc[2*p],   ahi, bl[0], bl[2]);
            mma16816(acc[2*p+1], ahi, bl[1], bl[3]);
            mma16816(acc[2*p],   alo, bh[0], bh[2]);
            mma16816(acc[2*p+1], alo, bh[1], bh[3]);
        }
    }
}

__global__ void __launch_bounds__(256, 2)
mlp_tc_kernel(const float* __restrict__ feat, const float* __restrict__ agg,
              const float* __restrict__ W1, const float* __restrict__ b1,
              const float* __restrict__ W2, const float* __restrict__ b2,
              const float* __restrict__ eps_p,
              float* __restrict__ h_out, float* __restrict__ out, int N) {
    extern __shared__ char sm[];
    const uint32_t smb = smem_u32(sm);
    const int tid = threadIdx.x;
    const int wid = tid >> 5;
    const int lane = tid & 31;
    const int m0 = (wid & 3) * 16;     // 4 m-tiles of 16 rows
    const int wn = wid >> 2;           // 2 n-halves of 64 cols
    const int row0 = blockIdx.x * BM;
    const float eps1 = 1.f + __ldg(eps_p);

    const float4* feat4 = (const float4*)feat;
    const float4* agg4  = (const float4*)agg;
    float* sB1 = (float*)(sm + SM_B1);
    float* sB2 = (float*)(sm + SM_B2);

    if (tid < 128) {
        sB1[tid] = __ldg(b1 + tid);
        sB2[tid] = __ldg(b2 + tid);
    }

    // ---- stage x = (1+eps)*feat + agg as bf16 hi/lo (64 rows) ----
    #pragma unroll
    for (int i = 0; i < 4; i++) {
        int tt = tid + i * 256;            // 1024 tasks: 64 rows x 16 kg
        int tr = tt >> 4, kg = tt & 15;
        int grow = row0 + tr;
        float v[8];
        if (grow < N) {
            float4 f0 = __ldg(feat4 + (size_t)grow * 32 + kg * 2);
            float4 f1 = __ldg(feat4 + (size_t)grow * 32 + kg * 2 + 1);
            float4 a0 = __ldg(agg4  + (size_t)grow * 32 + kg * 2);
            float4 a1 = __ldg(agg4  + (size_t)grow * 32 + kg * 2 + 1);
            v[0] = fmaf(eps1, f0.x, a0.x); v[1] = fmaf(eps1, f0.y, a0.y);
            v[2] = fmaf(eps1, f0.z, a0.z); v[3] = fmaf(eps1, f0.w, a0.w);
            v[4] = fmaf(eps1, f1.x, a1.x); v[5] = fmaf(eps1, f1.y, a1.y);
            v[6] = fmaf(eps1, f1.z, a1.z); v[7] = fmaf(eps1, f1.w, a1.w);
        } else {
            #pragma unroll
            for (int j = 0; j < 8; j++) v[j] = 0.f;
        }
        uint32_t hi[4], lo[4];
        split8(v, hi, lo);
        uint32_t off = (uint32_t)tr * LDB_B + (uint32_t)kg * 16;
        *(uint4*)(sm + SM_XHI + off) = make_uint4(hi[0], hi[1], hi[2], hi[3]);
        *(uint4*)(sm + SM_XLO + off) = make_uint4(lo[0], lo[1], lo[2], lo[3]);
    }

    // ---- stage W1 ----
    stage_w(sm, W1, tid);
    __syncthreads();

    // ---- layer 1 ----
    float acc[8][4];
    #pragma unroll
    for (int t = 0; t < 8; t++)
        #pragma unroll
        for (int j = 0; j < 4; j++) acc[t][j] = 0.f;
    do_layer(smb, m0, wn, lane, acc);
    __syncthreads();   // layer-1 reads of X and W1 complete

    // writeback h1 = leaky(acc + b1) into X tiles; restage W2 over W1
    {
        const int r0 = m0 + (lane >> 2);
        const int c0 = 2 * (lane & 3);
        #pragma unroll
        for (int p = 0; p < 4; p++) {
            #pragma unroll
            for (int s = 0; s < 2; s++) {
                int c = (wn * 4 + p) * 16 + s * 8 + c0;
                float v0 = leaky(acc[2*p+s][0] + sB1[c]);
                float v1 = leaky(acc[2*p+s][1] + sB1[c + 1]);
                float v2 = leaky(acc[2*p+s][2] + sB1[c]);
                float v3 = leaky(acc[2*p+s][3] + sB1[c + 1]);
                uint32_t h01, l01, h23, l23;
                split2(v0, v1, h01, l01);
                split2(v2, v3, h23, l23);
                uint32_t o0 = (uint32_t)r0 * LDB_B + (uint32_t)c * 2;
                uint32_t o1 = o0 + 8u * LDB_B;
                *(uint32_t*)(sm + SM_XHI + o0) = h01;
                *(uint32_t*)(sm + SM_XLO + o0) = l01;
                *(uint32_t*)(sm + SM_XHI + o1) = h23;
                *(uint32_t*)(sm + SM_XLO + o1) = l23;
            }
        }
    }
    stage_w(sm, W2, tid);
    __syncthreads();

    // ---- layer 2 ----
    #pragma unroll
    for (int t = 0; t < 8; t++)
        #pragma unroll
        for (int j = 0; j < 4; j++) acc[t][j] = 0.f;
    do_layer(smb, m0, wn, lane, acc);

    // ---- epilogue: stage h2 = leaky(acc + b2) as fp32 (reuse WHI region) ----
    __syncthreads();   // layer-2 reads of W done before clobbering
    {
        float* fst = (float*)(sm + SM_FST);
        const int r0 = m0 + (lane >> 2);
        const int c0 = 2 * (lane & 3);
        #pragma unroll
        for (int p = 0; p < 4; p++) {
            #pragma unroll
            for (int s = 0; s < 2; s++) {
                int c = (wn * 4 + p) * 16 + s * 8 + c0;
                float v0 = leaky(acc[2*p+s][0] + sB2[c]);
                float v1 = leaky(acc[2*p+s][1] + sB2[c + 1]);
                float v2 = leaky(acc[2*p+s][2] + sB2[c]);
                float v3 = leaky(acc[2*p+s][3] + sB2[c + 1]);
                *(float2*)(fst + (size_t)r0 * LDF + c)       = make_float2(v0, v1);
                *(float2*)(fst + (size_t)(r0 + 8) * LDF + c) = make_float2(v2, v3);
            }
        }
    }
    __syncthreads();

    // coalesced final writes: out = h2 + feat; h_out = h2
    {
        const float* fst = (const float*)(sm + SM_FST);
        #pragma unroll
        for (int i = 0; i < 8; i++) {
            int idx = tid + i * 256;          // 2048 float4 tasks
            int r = idx >> 5, c4 = idx & 31;
            int grow = row0 + r;
            if (grow >= N) continue;
            const float* p = fst + (size_t)r * LDF + c4 * 4;
            float4 h = make_float4(p[0], p[1], p[2], p[3]);
            float4 fv = __ldg(feat4 + (size_t)grow * 32 + c4);
            ((float4*)out)[(size_t)grow * 32 + c4] =
                make_float4(h.x + fv.x, h.y + fv.y, h.z + fv.z, h.w + fv.w);
            if (h_out)
                ((float4*)h_out)[(size_t)grow * 32 + c4] = h;
        }
    }
}

extern "C" void kernel_launch(void* const* d_in, const int* in_sizes, int n_in,
                              void* d_out, int out_size) {
    const float* feat_row = (const float*)d_in[0];
    const float* feat_col = (const float*)d_in[1];
    const int*   src_c2r  = (const int*)d_in[2];
    const int*   dst_c2r  = (const int*)d_in[3];
    const float* w_c2r    = (const float*)d_in[4];
    const int*   src_r2c  = (const int*)d_in[5];
    const int*   dst_r2c  = (const int*)d_in[6];
    const float* w_r2c    = (const float*)d_in[7];
    const float* W1_c2r   = (const float*)d_in[8];
    const float* b1_c2r   = (const float*)d_in[9];
    const float* W2_c2r   = (const float*)d_in[10];
    const float* b2_c2r   = (const float*)d_in[11];
    const float* W1_r2c   = (const float*)d_in[12];
    const float* b1_r2c   = (const float*)d_in[13];
    const float* W2_r2c   = (const float*)d_in[14];
    const float* b2_r2c   = (const float*)d_in[15];
    const float* eps_c2r  = (const float*)d_in[16];
    const float* eps_r2c  = (const float*)d_in[17];

    const int E = in_sizes[2];

    float* out_row = (float*)d_out;
    float* out_col = out_row + (size_t)NROW * D;

    float *agg1, *agg2, *hrow;
    cudaGetSymbolAddress((void**)&agg1, g_agg1);
    cudaGetSymbolAddress((void**)&agg2, g_agg2);
    cudaGetSymbolAddress((void**)&hrow, g_hrow);

    cudaFuncSetAttribute(mlp_tc_kernel, cudaFuncAttributeMaxDynamicSharedMemorySize, SM_TOTAL);

    const int n4 = NROW * D / 4;
    const int zgrid = (n4 + 255) / 256;
    const int egrid = (int)(((long long)E * 32 + 255) / 256);
    const int g_row = (NROW + BM - 1) / BM;
    const int g_col = (NCOL + BM - 1) / BM;

    // zero both agg buffers up front
    zero_kernel<<<zgrid, 256>>>((float4*)agg1, n4);
    zero_kernel<<<zgrid, 256>>>((float4*)agg2, n4);
    // col -> row
    agg_kernel<<<egrid, 256>>>((const float4*)feat_col, src_c2r, dst_c2r, w_c2r, agg1, E);
    mlp_tc_kernel<<<g_row, 256, SM_TOTAL>>>(feat_row, agg1, W1_c2r, b1_c2r, W2_c2r, b2_c2r,
                                            eps_c2r, hrow, out_row, NROW);
    // row -> col (uses updated h_row)
    agg_kernel<<<egrid, 256>>>((const float4*)hrow, src_r2c, dst_r2c, w_r2c, agg2, E);
    mlp_tc_kernel<<<g_col, 256, SM_TOTAL>>>(feat_col, agg2, W1_r2c, b1_r2c, W2_r2c, b2_r2c,
                                            eps_r2c, nullptr, out_col, NCOL);
}

// round 7
// speedup vs baseline: 2.1280x; 1.0657x over previous
#include <cuda_runtime.h>
#include <cuda_bf16.h>
#include <cstdint>

#define D      128
#define NROW   50000
#define NCOL   50000
#define BM     64

// bf16 tile geometry (row stride 272B, conflict-spread for ldmatrix)
#define LDB_B   272
#define XTILE_B (64 * LDB_B)         // 17408
#define WTILE_B (128 * LDB_B)        // 34816
#define WTILE_U4 (WTILE_B / 16)      // 2176

// Scratch (alloc-free rule: __device__ globals)
__device__ float g_agg1[(size_t)NROW * D];
__device__ float g_agg2[(size_t)NCOL * D];
__device__ float g_hrow[(size_t)NROW * D];
__device__ uint4 g_wt[4][2][WTILE_U4];   // [matrix][hi/lo][tile bytes]

__device__ __forceinline__ float leaky(float v) { return v >= 0.f ? v : 0.01f * v; }

__global__ void zero_kernel(float4* __restrict__ p, int n4) {
    int i = blockIdx.x * blockDim.x + threadIdx.x;
    if (i < n4) p[i] = make_float4(0.f, 0.f, 0.f, 0.f);
}

// One warp per edge; one red.global.add.v4.f32 per lane.
__global__ void agg_kernel(const float4* __restrict__ feat,
                           const int* __restrict__ src,
                           const int* __restrict__ dst,
                           const float* __restrict__ w,
                           float* __restrict__ agg, int E) {
    long long t = (long long)blockIdx.x * blockDim.x + threadIdx.x;
    int e = (int)(t >> 5);
    if (e >= E) return;
    int lane = (int)(t & 31);
    int s = __ldg(src + e);
    int d = __ldg(dst + e);
    float wt = __ldg(w + e);
    float4 v = __ldg(feat + (size_t)s * 32 + lane);
    float* a = agg + (size_t)d * D + lane * 4;
    asm volatile("red.global.add.v4.f32 [%0], {%1, %2, %3, %4};"
                 :: "l"(a), "f"(v.x * wt), "f"(v.y * wt), "f"(v.z * wt), "f"(v.w * wt)
                 : "memory");
}

static __device__ __forceinline__ void split8(const float* x, uint32_t* hi, uint32_t* lo) {
    #pragma unroll
    for (int j = 0; j < 4; j++) {
        __nv_bfloat16 h0 = __float2bfloat16(x[2*j]);
        __nv_bfloat16 h1 = __float2bfloat16(x[2*j+1]);
        __nv_bfloat16 l0 = __float2bfloat16(x[2*j]   - __bfloat162float(h0));
        __nv_bfloat16 l1 = __float2bfloat16(x[2*j+1] - __bfloat162float(h1));
        hi[j] = (uint32_t)__bfloat16_as_ushort(h0) | ((uint32_t)__bfloat16_as_ushort(h1) << 16);
        lo[j] = (uint32_t)__bfloat16_as_ushort(l0) | ((uint32_t)__bfloat16_as_ushort(l1) << 16);
    }
}

static __device__ __forceinline__ void split2(float x0, float x1, uint32_t& hi, uint32_t& lo) {
    __nv_bfloat16 h0 = __float2bfloat16(x0);
    __nv_bfloat16 h1 = __float2bfloat16(x1);
    __nv_bfloat16 l0 = __float2bfloat16(x0 - __bfloat162float(h0));
    __nv_bfloat16 l1 = __float2bfloat16(x1 - __bfloat162float(h1));
    hi = (uint32_t)__bfloat16_as_ushort(h0) | ((uint32_t)__bfloat16_as_ushort(h1) << 16);
    lo = (uint32_t)__bfloat16_as_ushort(l0) | ((uint32_t)__bfloat16_as_ushort(l1) << 16);
}

// Pre-split all 4 weight matrices into bf16 hi/lo tiles (transposed, final
// smem byte layout). grid = 32 blocks x 256 thr = 8192 tasks.
__global__ void split_w_kernel(const float* __restrict__ Wa, const float* __restrict__ Wb,
                               const float* __restrict__ Wc, const float* __restrict__ Wd) {
    int task = blockIdx.x * blockDim.x + threadIdx.x;   // 0..8191
    int m = task >> 11;                                 // matrix 0..3
    int tt = task & 2047;                               // n x kg
    int n = tt & 127, kg = tt >> 7;
    const float* W = (m == 0) ? Wa : (m == 1) ? Wb : (m == 2) ? Wc : Wd;
    float v[8];
    #pragma unroll
    for (int j = 0; j < 8; j++) v[j] = __ldg(W + (kg * 8 + j) * D + n);
    uint32_t hi[4], lo[4];
    split8(v, hi, lo);
    uint32_t idx = ((uint32_t)n * LDB_B + (uint32_t)kg * 16) >> 4;
    g_wt[m][0][idx] = make_uint4(hi[0], hi[1], hi[2], hi[3]);
    g_wt[m][1][idx] = make_uint4(lo[0], lo[1], lo[2], lo[3]);
}

// ---------------- HMMA (mma.sync) MLP ----------------
#define SM_XHI  0
#define SM_XLO  (SM_XHI + XTILE_B)
#define SM_WHI  (SM_XLO + XTILE_B)
#define SM_WLO  (SM_WHI + WTILE_B)
#define SM_B1   (SM_WLO + WTILE_B)
#define SM_B2   (SM_B1 + 512)
#define SM_TOTAL (SM_B2 + 512)        // 105472 bytes -> 2 CTAs/SM
// fp32 epilogue staging reuses the (dead) WHI region: 64 x 132 floats
#define SM_FST  SM_WHI
#define LDF     132

static __device__ __forceinline__ uint32_t smem_u32(const void* p) {
    uint32_t a;
    asm("{ .reg .u64 t; cvta.to.shared.u64 t, %1; cvt.u32.u64 %0, t; }" : "=r"(a) : "l"(p));
    return a;
}

static __device__ __forceinline__ void ldsm4(uint32_t* r, uint32_t addr) {
    asm volatile("ldmatrix.sync.aligned.m8n8.x4.shared.b16 {%0,%1,%2,%3}, [%4];"
                 : "=r"(r[0]), "=r"(r[1]), "=r"(r[2]), "=r"(r[3]) : "r"(addr));
}

static __device__ __forceinline__ void mma16816(float* d, const uint32_t* a,
                                                uint32_t b0, uint32_t b1) {
    asm volatile("mma.sync.aligned.m16n8k16.row.col.f32.bf16.bf16.f32 "
                 "{%0,%1,%2,%3}, {%4,%5,%6,%7}, {%8,%9}, {%0,%1,%2,%3};"
                 : "+f"(d[0]), "+f"(d[1]), "+f"(d[2]), "+f"(d[3])
                 : "r"(a[0]), "r"(a[1]), "r"(a[2]), "r"(a[3]), "r"(b0), "r"(b1));
}

// async-stage one pre-split weight pair into SM_WHI/SM_WLO (verbatim copy)
static __device__ __forceinline__ void stage_w_async(uint32_t smb, const uint4* __restrict__ hi,
                                                     const uint4* __restrict__ lo, int tid) {
    for (int i = tid; i < WTILE_U4; i += 256) {
        uint32_t dh = smb + SM_WHI + (uint32_t)i * 16;
        uint32_t dl = smb + SM_WLO + (uint32_t)i * 16;
        asm volatile("cp.async.cg.shared.global [%0], [%1], 16;" :: "r"(dh), "l"(hi + i));
        asm volatile("cp.async.cg.shared.global [%0], [%1], 16;" :: "r"(dl), "l"(lo + i));
    }
    asm volatile("cp.async.commit_group;" ::: "memory");
}
static __device__ __forceinline__ void wait_cp() {
    asm volatile("cp.async.wait_group 0;" ::: "memory");
}

// One layer for one warp: acc[8][4] += X(m0..m0+15, :) @ W^T over n-cols
// [wn*64, wn*64+64). 3-way bf16 split, interleaved accumulators.
static __device__ __forceinline__ void do_layer(uint32_t smb, int m0, int wn, int lane,
                                                float acc[8][4]) {
    const int rsel = lane & 15;
    const uint32_t koff = (uint32_t)((lane >> 4) << 4);
    #pragma unroll
    for (int kk = 0; kk < 8; kk++) {
        uint32_t rowk = (uint32_t)kk * 32 + koff;
        uint32_t ahi[4], alo[4];
        ldsm4(ahi, smb + SM_XHI + (uint32_t)(m0 + rsel) * LDB_B + rowk);
        ldsm4(alo, smb + SM_XLO + (uint32_t)(m0 + rsel) * LDB_B + rowk);
        #pragma unroll
        for (int p = 0; p < 4; p++) {
            uint32_t boff = (uint32_t)((wn * 4 + p) * 16 + rsel) * LDB_B + rowk;
            uint32_t bh[4], bl[4];
            ldsm4(bh, smb + SM_WHI + boff);
            ldsm4(bl, smb + SM_WLO + boff);
            mma16816(acc[2*p],   ahi, bh[0], bh[2]);
            mma16816(acc[2*p+1], ahi, bh[1], bh[3]);
            mma16816(acc[2*p],   ahi, bl[0], bl[2]);
            mma16816(acc[2*p+1], ahi, bl[1], bl[3]);
            mma16816(acc[2*p],   alo, bh[0], bh[2]);
            mma16816(acc[2*p+1], alo, bh[1], bh[3]);
        }
    }
}

__global__ void __launch_bounds__(256, 2)
mlp_tc_kernel(const float* __restrict__ feat, const float* __restrict__ agg,
              const uint4* __restrict__ w1hi, const uint4* __restrict__ w1lo,
              const uint4* __restrict__ w2hi, const uint4* __restrict__ w2lo,
              const float* __restrict__ b1, const float* __restrict__ b2,
              const float* __restrict__ eps_p,
              float* __restrict__ h_out, float* __restrict__ out, int N) {
    extern __shared__ char sm[];
    const uint32_t smb = smem_u32(sm);
    const int tid = threadIdx.x;
    const int wid = tid >> 5;
    const int lane = tid & 31;
    const int m0 = (wid & 3) * 16;     // 4 m-tiles of 16 rows
    const int wn = wid >> 2;           // 2 n-halves of 64 cols
    const int row0 = blockIdx.x * BM;
    const float eps1 = 1.f + __ldg(eps_p);

    const float4* feat4 = (const float4*)feat;
    const float4* agg4  = (const float4*)agg;
    float* sB1 = (float*)(sm + SM_B1);
    float* sB2 = (float*)(sm + SM_B2);

    // kick off W1 async copy first (overlaps the X staging below)
    stage_w_async(smb, w1hi, w1lo, tid);

    if (tid < 128) {
        sB1[tid] = __ldg(b1 + tid);
        sB2[tid] = __ldg(b2 + tid);
    }

    // ---- stage x = (1+eps)*feat + agg as bf16 hi/lo (64 rows) ----
    #pragma unroll
    for (int i = 0; i < 4; i++) {
        int tt = tid + i * 256;            // 1024 tasks: 64 rows x 16 kg
        int tr = tt >> 4, kg = tt & 15;
        int grow = row0 + tr;
        float v[8];
        if (grow < N) {
            float4 f0 = __ldg(feat4 + (size_t)grow * 32 + kg * 2);
            float4 f1 = __ldg(feat4 + (size_t)grow * 32 + kg * 2 + 1);
            float4 a0 = __ldg(agg4  + (size_t)grow * 32 + kg * 2);
            float4 a1 = __ldg(agg4  + (size_t)grow * 32 + kg * 2 + 1);
            v[0] = fmaf(eps1, f0.x, a0.x); v[1] = fmaf(eps1, f0.y, a0.y);
            v[2] = fmaf(eps1, f0.z, a0.z); v[3] = fmaf(eps1, f0.w, a0.w);
            v[4] = fmaf(eps1, f1.x, a1.x); v[5] = fmaf(eps1, f1.y, a1.y);
            v[6] = fmaf(eps1, f1.z, a1.z); v[7] = fmaf(eps1, f1.w, a1.w);
        } else {
            #pragma unroll
            for (int j = 0; j < 8; j++) v[j] = 0.f;
        }
        uint32_t hi[4], lo[4];
        split8(v, hi, lo);
        uint32_t off = (uint32_t)tr * LDB_B + (uint32_t)kg * 16;
        *(uint4*)(sm + SM_XHI + off) = make_uint4(hi[0], hi[1], hi[2], hi[3]);
        *(uint4*)(sm + SM_XLO + off) = make_uint4(lo[0], lo[1], lo[2], lo[3]);
    }
    wait_cp();
    __syncthreads();

    // ---- layer 1 ----
    float acc[8][4];
    #pragma unroll
    for (int t = 0; t < 8; t++)
        #pragma unroll
        for (int j = 0; j < 4; j++) acc[t][j] = 0.f;
    do_layer(smb, m0, wn, lane, acc);
    __syncthreads();   // layer-1 reads of X and W1 complete

    // restage W2 (async, overlaps h1 writeback)
    stage_w_async(smb, w2hi, w2lo, tid);

    // writeback h1 = leaky(acc + b1) into X tiles
    {
        const int r0 = m0 + (lane >> 2);
        const int c0 = 2 * (lane & 3);
        #pragma unroll
        for (int p = 0; p < 4; p++) {
            #pragma unroll
            for (int s = 0; s < 2; s++) {
                int c = (wn * 4 + p) * 16 + s * 8 + c0;
                float v0 = leaky(acc[2*p+s][0] + sB1[c]);
                float v1 = leaky(acc[2*p+s][1] + sB1[c + 1]);
                float v2 = leaky(acc[2*p+s][2] + sB1[c]);
                float v3 = leaky(acc[2*p+s][3] + sB1[c + 1]);
                uint32_t h01, l01, h23, l23;
                split2(v0, v1, h01, l01);
                split2(v2, v3, h23, l23);
                uint32_t o0 = (uint32_t)r0 * LDB_B + (uint32_t)c * 2;
                uint32_t o1 = o0 + 8u * LDB_B;
                *(uint32_t*)(sm + SM_XHI + o0) = h01;
                *(uint32_t*)(sm + SM_XLO + o0) = l01;
                *(uint32_t*)(sm + SM_XHI + o1) = h23;
                *(uint32_t*)(sm + SM_XLO + o1) = l23;
            }
        }
    }
    wait_cp();
    __syncthreads();

    // ---- layer 2 ----
    #pragma unroll
    for (int t = 0; t < 8; t++)
        #pragma unroll
        for (int j = 0; j < 4; j++) acc[t][j] = 0.f;
    do_layer(smb, m0, wn, lane, acc);

    // ---- epilogue: stage h2 = leaky(acc + b2) as fp32 (reuse WHI region) ----
    __syncthreads();   // layer-2 reads of W done before clobbering
    {
        float* fst = (float*)(sm + SM_FST);
        const int r0 = m0 + (lane >> 2);
        const int c0 = 2 * (lane & 3);
        #pragma unroll
        for (int p = 0; p < 4; p++) {
            #pragma unroll
            for (int s = 0; s < 2; s++) {
                int c = (wn * 4 + p) * 16 + s * 8 + c0;
                float v0 = leaky(acc[2*p+s][0] + sB2[c]);
                float v1 = leaky(acc[2*p+s][1] + sB2[c + 1]);
                float v2 = leaky(acc[2*p+s][2] + sB2[c]);
                float v3 = leaky(acc[2*p+s][3] + sB2[c + 1]);
                *(float2*)(fst + (size_t)r0 * LDF + c)       = make_float2(v0, v1);
                *(float2*)(fst + (size_t)(r0 + 8) * LDF + c) = make_float2(v2, v3);
            }
        }
    }
    __syncthreads();

    // coalesced final writes: out = h2 + feat; h_out = h2
    {
        const float* fst = (const float*)(sm + SM_FST);
        #pragma unroll
        for (int i = 0; i < 8; i++) {
            int idx = tid + i * 256;          // 2048 float4 tasks
            int r = idx >> 5, c4 = idx & 31;
            int grow = row0 + r;
            if (grow >= N) continue;
            const float* p = fst + (size_t)r * LDF + c4 * 4;
            float4 h = make_float4(p[0], p[1], p[2], p[3]);
            float4 fv = __ldg(feat4 + (size_t)grow * 32 + c4);
            ((float4*)out)[(size_t)grow * 32 + c4] =
                make_float4(h.x + fv.x, h.y + fv.y, h.z + fv.z, h.w + fv.w);
            if (h_out)
                ((float4*)h_out)[(size_t)grow * 32 + c4] = h;
        }
    }
}

extern "C" void kernel_launch(void* const* d_in, const int* in_sizes, int n_in,
                              void* d_out, int out_size) {
    const float* feat_row = (const float*)d_in[0];
    const float* feat_col = (const float*)d_in[1];
    const int*   src_c2r  = (const int*)d_in[2];
    const int*   dst_c2r  = (const int*)d_in[3];
    const float* w_c2r    = (const float*)d_in[4];
    const int*   src_r2c  = (const int*)d_in[5];
    const int*   dst_r2c  = (const int*)d_in[6];
    const float* w_r2c    = (const float*)d_in[7];
    const float* W1_c2r   = (const float*)d_in[8];
    const float* b1_c2r   = (const float*)d_in[9];
    const float* W2_c2r   = (const float*)d_in[10];
    const float* b2_c2r   = (const float*)d_in[11];
    const float* W1_r2c   = (const float*)d_in[12];
    const float* b1_r2c   = (const float*)d_in[13];
    const float* W2_r2c   = (const float*)d_in[14];
    const float* b2_r2c   = (const float*)d_in[15];
    const float* eps_c2r  = (const float*)d_in[16];
    const float* eps_r2c  = (const float*)d_in[17];

    const int E = in_sizes[2];

    float* out_row = (float*)d_out;
    float* out_col = out_row + (size_t)NROW * D;

    float *agg1, *agg2, *hrow;
    uint4* wt;
    cudaGetSymbolAddress((void**)&agg1, g_agg1);
    cudaGetSymbolAddress((void**)&agg2, g_agg2);
    cudaGetSymbolAddress((void**)&hrow, g_hrow);
    cudaGetSymbolAddress((void**)&wt,   g_wt);
    const uint4* w1hi_a = wt + 0 * 2 * WTILE_U4;
    const uint4* w1lo_a = wt + (0 * 2 + 1) * WTILE_U4;
    const uint4* w2hi_a = wt + 1 * 2 * WTILE_U4;
    const uint4* w2lo_a = wt + (1 * 2 + 1) * WTILE_U4;
    const uint4* w1hi_b = wt + 2 * 2 * WTILE_U4;
    const uint4* w1lo_b = wt + (2 * 2 + 1) * WTILE_U4;
    const uint4* w2hi_b = wt + 3 * 2 * WTILE_U4;
    const uint4* w2lo_b = wt + (3 * 2 + 1) * WTILE_U4;

    cudaFuncSetAttribute(mlp_tc_kernel, cudaFuncAttributeMaxDynamicSharedMemorySize, SM_TOTAL);

    const int n4 = NROW * D / 4;
    const int zgrid = (n4 + 255) / 256;
    const int egrid = (int)(((long long)E * 32 + 255) / 256);
    const int g_row = (NROW + BM - 1) / BM;
    const int g_col = (NCOL + BM - 1) / BM;

    // prep: zero agg buffers, pre-split weights
    zero_kernel<<<zgrid, 256>>>((float4*)agg1, n4);
    zero_kernel<<<zgrid, 256>>>((float4*)agg2, n4);
    split_w_kernel<<<32, 256>>>(W1_c2r, W2_c2r, W1_r2c, W2_r2c);
    // col -> row
    agg_kernel<<<egrid, 256>>>((const float4*)feat_col, src_c2r, dst_c2r, w_c2r, agg1, E);
    mlp_tc_kernel<<<g_row, 256, SM_TOTAL>>>(feat_row, agg1, w1hi_a, w1lo_a, w2hi_a, w2lo_a,
                                            b1_c2r, b2_c2r, eps_c2r, hrow, out_row, NROW);
    // row -> col (uses updated h_row)
    agg_kernel<<<egrid, 256>>>((const float4*)hrow, src_r2c, dst_r2c, w_r2c, agg2, E);
    mlp_tc_kernel<<<g_col, 256, SM_TOTAL>>>(feat_col, agg2, w1hi_b, w1lo_b, w2hi_b, w2lo_b,
                                            b1_r2c, b2_r2c, eps_r2c, nullptr, out_col, NCOL);
}

// round 8
// speedup vs baseline: 2.7449x; 1.2899x over previous
#include <cuda_runtime.h>
#include <cuda_bf16.h>
#include <cstdint>

#define D      128
#define NROW   50000
#define NCOL   50000
#define NTOT   (NROW + NCOL)
#define BM     64

// bf16 tile geometry (row stride 272B, conflict-spread for ldmatrix)
#define LDB_B   272
#define XTILE_B (64 * LDB_B)
#define WTILE_B (128 * LDB_B)
#define WTILE_U4 (WTILE_B / 16)

// Scratch (alloc-free rule: __device__ globals)
__device__ float g_agg1[(size_t)NROW * D];
__device__ float g_agg2[(size_t)NCOL * D];
__device__ float g_hrow[(size_t)NROW * D];
__device__ uint4 g_wt[4][2][WTILE_U4];
__device__ int   g_cnt[NTOT];          // per-dst degree (both graphs concatenated)
__device__ int   g_ptr[NTOT + 1];      // CSR row pointers (joint exclusive scan)
__device__ int   g_cur[NTOT];          // scatter cursors
__device__ int   g_bsum[128];          // block sums for scan
__device__ int2  g_edges[1200000];     // packed (src, w_bits), both graphs

__device__ __forceinline__ float leaky(float v) { return v >= 0.f ? v : 0.01f * v; }

// ---------------- CSR build ----------------
__global__ void zero_cnt_kernel(int* __restrict__ cnt, int n) {
    int i = blockIdx.x * blockDim.x + threadIdx.x;
    if (i < n) cnt[i] = 0;
}

__global__ void hist_kernel(const int* __restrict__ dst, int* __restrict__ cnt,
                            int E, int off) {
    int e = blockIdx.x * blockDim.x + threadIdx.x;
    if (e < E) atomicAdd(cnt + off + __ldg(dst + e), 1);
}

// block-local exclusive scan (1024 elems / block) + block totals
__global__ void scan_blk_kernel(const int* __restrict__ cnt, int* __restrict__ ptr,
                                int* __restrict__ bsum, int n) {
    __shared__ int wsum[32];
    int tid = threadIdx.x, lane = tid & 31, wid = tid >> 5;
    int i = blockIdx.x * 1024 + tid;
    int x = (i < n) ? cnt[i] : 0;
    int v = x;
    #pragma unroll
    for (int o = 1; o < 32; o <<= 1) { int t = __shfl_up_sync(~0u, v, o); if (lane >= o) v += t; }
    if (lane == 31) wsum[wid] = v;
    __syncthreads();
    if (wid == 0) {
        int s = wsum[lane];
        #pragma unroll
        for (int o = 1; o < 32; o <<= 1) { int t = __shfl_up_sync(~0u, s, o); if (lane >= o) s += t; }
        wsum[lane] = s;
    }
    __syncthreads();
    int woff = wid ? wsum[wid - 1] : 0;
    if (i < n) ptr[i] = woff + v - x;
    if (tid == 1023) bsum[blockIdx.x] = wsum[31];
}

// single-block exclusive scan of block totals (nb <= 128)
__global__ void scan_tot_kernel(int* __restrict__ bsum, int nb) {
    __shared__ int tmp[128];
    int tid = threadIdx.x;
    int x = (tid < nb) ? bsum[tid] : 0;
    tmp[tid] = x;
    __syncthreads();
    for (int o = 1; o < 128; o <<= 1) {
        int t = (tid >= o) ? tmp[tid - o] : 0;
        __syncthreads();
        tmp[tid] += t;
        __syncthreads();
    }
    if (tid < nb) bsum[tid] = tmp[tid] - x;
}

__global__ void scan_add_kernel(int* __restrict__ ptr, int* __restrict__ cur,
                                const int* __restrict__ bsum, int n, int total) {
    int i = blockIdx.x * blockDim.x + threadIdx.x;
    if (i < n) {
        int v = ptr[i] + bsum[i >> 10];
        ptr[i] = v;
        cur[i] = v;
    }
    if (i == 0) ptr[n] = total;
}

__global__ void scatter_kernel(const int* __restrict__ src, const int* __restrict__ dst,
                               const float* __restrict__ w, int* __restrict__ cur,
                               int2* __restrict__ edges, int E, int off) {
    int e = blockIdx.x * blockDim.x + threadIdx.x;
    if (e >= E) return;
    int pos = atomicAdd(cur + off + __ldg(dst + e), 1);
    edges[pos] = make_int2(__ldg(src + e), __float_as_int(__ldg(w + e)));
}

// ---------------- CSR aggregation: one warp per dst node ----------------
__global__ void csr_agg_kernel(const float4* __restrict__ feat,
                               const int* __restrict__ ptr,
                               const int2* __restrict__ edges,
                               float* __restrict__ agg, int n, int off) {
    int t = blockIdx.x * blockDim.x + threadIdx.x;
    int node = t >> 5;
    if (node >= n) return;
    int lane = t & 31;
    int beg = __ldg(ptr + off + node);
    int end = __ldg(ptr + off + node + 1);
    float4 a0 = make_float4(0.f, 0.f, 0.f, 0.f);
    float4 a1 = make_float4(0.f, 0.f, 0.f, 0.f);
    int i = beg;
    for (; i + 2 <= end; i += 2) {
        int2 e0 = __ldg(edges + i);
        int2 e1 = __ldg(edges + i + 1);
        float w0 = __int_as_float(e0.y), w1 = __int_as_float(e1.y);
        float4 v0 = __ldg(feat + (size_t)e0.x * 32 + lane);
        float4 v1 = __ldg(feat + (size_t)e1.x * 32 + lane);
        a0.x = fmaf(v0.x, w0, a0.x); a0.y = fmaf(v0.y, w0, a0.y);
        a0.z = fmaf(v0.z, w0, a0.z); a0.w = fmaf(v0.w, w0, a0.w);
        a1.x = fmaf(v1.x, w1, a1.x); a1.y = fmaf(v1.y, w1, a1.y);
        a1.z = fmaf(v1.z, w1, a1.z); a1.w = fmaf(v1.w, w1, a1.w);
    }
    if (i < end) {
        int2 e0 = __ldg(edges + i);
        float w0 = __int_as_float(e0.y);
        float4 v0 = __ldg(feat + (size_t)e0.x * 32 + lane);
        a0.x = fmaf(v0.x, w0, a0.x); a0.y = fmaf(v0.y, w0, a0.y);
        a0.z = fmaf(v0.z, w0, a0.z); a0.w = fmaf(v0.w, w0, a0.w);
    }
    ((float4*)agg)[(size_t)node * 32 + lane] =
        make_float4(a0.x + a1.x, a0.y + a1.y, a0.z + a1.z, a0.w + a1.w);
}

// ---------------- weight pre-split ----------------
static __device__ __forceinline__ void split8(const float* x, uint32_t* hi, uint32_t* lo) {
    #pragma unroll
    for (int j = 0; j < 4; j++) {
        __nv_bfloat16 h0 = __float2bfloat16(x[2*j]);
        __nv_bfloat16 h1 = __float2bfloat16(x[2*j+1]);
        __nv_bfloat16 l0 = __float2bfloat16(x[2*j]   - __bfloat162float(h0));
        __nv_bfloat16 l1 = __float2bfloat16(x[2*j+1] - __bfloat162float(h1));
        hi[j] = (uint32_t)__bfloat16_as_ushort(h0) | ((uint32_t)__bfloat16_as_ushort(h1) << 16);
        lo[j] = (uint32_t)__bfloat16_as_ushort(l0) | ((uint32_t)__bfloat16_as_ushort(l1) << 16);
    }
}

static __device__ __forceinline__ void split2(float x0, float x1, uint32_t& hi, uint32_t& lo) {
    __nv_bfloat16 h0 = __float2bfloat16(x0);
    __nv_bfloat16 h1 = __float2bfloat16(x1);
    __nv_bfloat16 l0 = __float2bfloat16(x0 - __bfloat162float(h0));
    __nv_bfloat16 l1 = __float2bfloat16(x1 - __bfloat162float(h1));
    hi = (uint32_t)__bfloat16_as_ushort(h0) | ((uint32_t)__bfloat16_as_ushort(h1) << 16);
    lo = (uint32_t)__bfloat16_as_ushort(l0) | ((uint32_t)__bfloat16_as_ushort(l1) << 16);
}

__global__ void split_w_kernel(const float* __restrict__ Wa, const float* __restrict__ Wb,
                               const float* __restrict__ Wc, const float* __restrict__ Wd) {
    int task = blockIdx.x * blockDim.x + threadIdx.x;   // 0..8191
    int m = task >> 11;
    int tt = task & 2047;
    int n = tt & 127, kg = tt >> 7;
    const float* W = (m == 0) ? Wa : (m == 1) ? Wb : (m == 2) ? Wc : Wd;
    float v[8];
    #pragma unroll
    for (int j = 0; j < 8; j++) v[j] = __ldg(W + (kg * 8 + j) * D + n);
    uint32_t hi[4], lo[4];
    split8(v, hi, lo);
    uint32_t idx = ((uint32_t)n * LDB_B + (uint32_t)kg * 16) >> 4;
    g_wt[m][0][idx] = make_uint4(hi[0], hi[1], hi[2], hi[3]);
    g_wt[m][1][idx] = make_uint4(lo[0], lo[1], lo[2], lo[3]);
}

// ---------------- HMMA (mma.sync) MLP ----------------
#define SM_XHI  0
#define SM_XLO  (SM_XHI + XTILE_B)
#define SM_WHI  (SM_XLO + XTILE_B)
#define SM_WLO  (SM_WHI + WTILE_B)
#define SM_B1   (SM_WLO + WTILE_B)
#define SM_B2   (SM_B1 + 512)
#define SM_TOTAL (SM_B2 + 512)        // 105472 bytes -> 2 CTAs/SM
#define SM_FST  SM_WHI
#define LDF     132

static __device__ __forceinline__ uint32_t smem_u32(const void* p) {
    uint32_t a;
    asm("{ .reg .u64 t; cvta.to.shared.u64 t, %1; cvt.u32.u64 %0, t; }" : "=r"(a) : "l"(p));
    return a;
}

static __device__ __forceinline__ void ldsm4(uint32_t* r, uint32_t addr) {
    asm volatile("ldmatrix.sync.aligned.m8n8.x4.shared.b16 {%0,%1,%2,%3}, [%4];"
                 : "=r"(r[0]), "=r"(r[1]), "=r"(r[2]), "=r"(r[3]) : "r"(addr));
}

static __device__ __forceinline__ void mma16816(float* d, const uint32_t* a,
                                                uint32_t b0, uint32_t b1) {
    asm volatile("mma.sync.aligned.m16n8k16.row.col.f32.bf16.bf16.f32 "
                 "{%0,%1,%2,%3}, {%4,%5,%6,%7}, {%8,%9}, {%0,%1,%2,%3};"
                 : "+f"(d[0]), "+f"(d[1]), "+f"(d[2]), "+f"(d[3])
                 : "r"(a[0]), "r"(a[1]), "r"(a[2]), "r"(a[3]), "r"(b0), "r"(b1));
}

static __device__ __forceinline__ void stage_w_async(uint32_t smb, const uint4* __restrict__ hi,
                                                     const uint4* __restrict__ lo, int tid) {
    for (int i = tid; i < WTILE_U4; i += 256) {
        uint32_t dh = smb + SM_WHI + (uint32_t)i * 16;
        uint32_t dl = smb + SM_WLO + (uint32_t)i * 16;
        asm volatile("cp.async.cg.shared.global [%0], [%1], 16;" :: "r"(dh), "l"(hi + i));
        asm volatile("cp.async.cg.shared.global [%0], [%1], 16;" :: "r"(dl), "l"(lo + i));
    }
    asm volatile("cp.async.commit_group;" ::: "memory");
}
static __device__ __forceinline__ void wait_cp() {
    asm volatile("cp.async.wait_group 0;" ::: "memory");
}

static __device__ __forceinline__ void do_layer(uint32_t smb, int m0, int wn, int lane,
                                                float acc[8][4]) {
    const int rsel = lane & 15;
    const uint32_t koff = (uint32_t)((lane >> 4) << 4);
    #pragma unroll
    for (int kk = 0; kk < 8; kk++) {
        uint32_t rowk = (uint32_t)kk * 32 + koff;
        uint32_t ahi[4], alo[4];
        ldsm4(ahi, smb + SM_XHI + (uint32_t)(m0 + rsel) * LDB_B + rowk);
        ldsm4(alo, smb + SM_XLO + (uint32_t)(m0 + rsel) * LDB_B + rowk);
        #pragma unroll
        for (int p = 0; p < 4; p++) {
            uint32_t boff = (uint32_t)((wn * 4 + p) * 16 + rsel) * LDB_B + rowk;
            uint32_t bh[4], bl[4];
            ldsm4(bh, smb + SM_WHI + boff);
            ldsm4(bl, smb + SM_WLO + boff);
            mma16816(acc[2*p],   ahi, bh[0], bh[2]);
            mma16816(acc[2*p+1], ahi, bh[1], bh[3]);
            mma16816(acc[2*p],   ahi, bl[0], bl[2]);
            mma16816(acc[2*p+1], ahi, bl[1], bl[3]);
            mma16816(acc[2*p],   alo, bh[0], bh[2]);
            mma16816(acc[2*p+1], alo, bh[1], bh[3]);
        }
    }
}

__global__ void __launch_bounds__(256, 2)
mlp_tc_kernel(const float* __restrict__ feat, const float* __restrict__ agg,
              const uint4* __restrict__ w1hi, const uint4* __restrict__ w1lo,
              const uint4* __restrict__ w2hi, const uint4* __restrict__ w2lo,
              const float* __restrict__ b1, const float* __restrict__ b2,
              const float* __restrict__ eps_p,
              float* __restrict__ h_out, float* __restrict__ out, int N) {
    extern __shared__ char sm[];
    const uint32_t smb = smem_u32(sm);
    const int tid = threadIdx.x;
    const int wid = tid >> 5;
    const int lane = tid & 31;
    const int m0 = (wid & 3) * 16;
    const int wn = wid >> 2;
    const int row0 = blockIdx.x * BM;
    const float eps1 = 1.f + __ldg(eps_p);

    const float4* feat4 = (const float4*)feat;
    const float4* agg4  = (const float4*)agg;
    float* sB1 = (float*)(sm + SM_B1);
    float* sB2 = (float*)(sm + SM_B2);

    stage_w_async(smb, w1hi, w1lo, tid);

    if (tid < 128) {
        sB1[tid] = __ldg(b1 + tid);
        sB2[tid] = __ldg(b2 + tid);
    }

    // ---- stage x = (1+eps)*feat + agg as bf16 hi/lo (64 rows) ----
    #pragma unroll
    for (int i = 0; i < 4; i++) {
        int tt = tid + i * 256;
        int tr = tt >> 4, kg = tt & 15;
        int grow = row0 + tr;
        float v[8];
        if (grow < N) {
            float4 f0 = __ldg(feat4 + (size_t)grow * 32 + kg * 2);
            float4 f1 = __ldg(feat4 + (size_t)grow * 32 + kg * 2 + 1);
            float4 a0 = __ldg(agg4  + (size_t)grow * 32 + kg * 2);
            float4 a1 = __ldg(agg4  + (size_t)grow * 32 + kg * 2 + 1);
            v[0] = fmaf(eps1, f0.x, a0.x); v[1] = fmaf(eps1, f0.y, a0.y);
            v[2] = fmaf(eps1, f0.z, a0.z); v[3] = fmaf(eps1, f0.w, a0.w);
            v[4] = fmaf(eps1, f1.x, a1.x); v[5] = fmaf(eps1, f1.y, a1.y);
            v[6] = fmaf(eps1, f1.z, a1.z); v[7] = fmaf(eps1, f1.w, a1.w);
        } else {
            #pragma unroll
            for (int j = 0; j < 8; j++) v[j] = 0.f;
        }
        uint32_t hi[4], lo[4];
        split8(v, hi, lo);
        uint32_t off = (uint32_t)tr * LDB_B + (uint32_t)kg * 16;
        *(uint4*)(sm + SM_XHI + off) = make_uint4(hi[0], hi[1], hi[2], hi[3]);
        *(uint4*)(sm + SM_XLO + off) = make_uint4(lo[0], lo[1], lo[2], lo[3]);
    }
    wait_cp();
    __syncthreads();

    // ---- layer 1 ----
    float acc[8][4];
    #pragma unroll
    for (int t = 0; t < 8; t++)
        #pragma unroll
        for (int j = 0; j < 4; j++) acc[t][j] = 0.f;
    do_layer(smb, m0, wn, lane, acc);
    __syncthreads();

    stage_w_async(smb, w2hi, w2lo, tid);

    // writeback h1 = leaky(acc + b1) into X tiles
    {
        const int r0 = m0 + (lane >> 2);
        const int c0 = 2 * (lane & 3);
        #pragma unroll
        for (int p = 0; p < 4; p++) {
            #pragma unroll
            for (int s = 0; s < 2; s++) {
                int c = (wn * 4 + p) * 16 + s * 8 + c0;
                float v0 = leaky(acc[2*p+s][0] + sB1[c]);
                float v1 = leaky(acc[2*p+s][1] + sB1[c + 1]);
                float v2 = leaky(acc[2*p+s][2] + sB1[c]);
                float v3 = leaky(acc[2*p+s][3] + sB1[c + 1]);
                uint32_t h01, l01, h23, l23;
                split2(v0, v1, h01, l01);
                split2(v2, v3, h23, l23);
                uint32_t o0 = (uint32_t)r0 * LDB_B + (uint32_t)c * 2;
                uint32_t o1 = o0 + 8u * LDB_B;
                *(uint32_t*)(sm + SM_XHI + o0) = h01;
                *(uint32_t*)(sm + SM_XLO + o0) = l01;
                *(uint32_t*)(sm + SM_XHI + o1) = h23;
                *(uint32_t*)(sm + SM_XLO + o1) = l23;
            }
        }
    }
    wait_cp();
    __syncthreads();

    // ---- layer 2 ----
    #pragma unroll
    for (int t = 0; t < 8; t++)
        #pragma unroll
        for (int j = 0; j < 4; j++) acc[t][j] = 0.f;
    do_layer(smb, m0, wn, lane, acc);

    __syncthreads();
    {
        float* fst = (float*)(sm + SM_FST);
        const int r0 = m0 + (lane >> 2);
        const int c0 = 2 * (lane & 3);
        #pragma unroll
        for (int p = 0; p < 4; p++) {
            #pragma unroll
            for (int s = 0; s < 2; s++) {
                int c = (wn * 4 + p) * 16 + s * 8 + c0;
                float v0 = leaky(acc[2*p+s][0] + sB2[c]);
                float v1 = leaky(acc[2*p+s][1] + sB2[c + 1]);
                float v2 = leaky(acc[2*p+s][2] + sB2[c]);
                float v3 = leaky(acc[2*p+s][3] + sB2[c + 1]);
                *(float2*)(fst + (size_t)r0 * LDF + c)       = make_float2(v0, v1);
                *(float2*)(fst + (size_t)(r0 + 8) * LDF + c) = make_float2(v2, v3);
            }
        }
    }
    __syncthreads();

    {
        const float* fst = (const float*)(sm + SM_FST);
        #pragma unroll
        for (int i = 0; i < 8; i++) {
            int idx = tid + i * 256;
            int r = idx >> 5, c4 = idx & 31;
            int grow = row0 + r;
            if (grow >= N) continue;
            const float* p = fst + (size_t)r * LDF + c4 * 4;
            float4 h = make_float4(p[0], p[1], p[2], p[3]);
            float4 fv = __ldg(feat4 + (size_t)grow * 32 + c4);
            ((float4*)out)[(size_t)grow * 32 + c4] =
                make_float4(h.x + fv.x, h.y + fv.y, h.z + fv.z, h.w + fv.w);
            if (h_out)
                ((float4*)h_out)[(size_t)grow * 32 + c4] = h;
        }
    }
}

extern "C" void kernel_launch(void* const* d_in, const int* in_sizes, int n_in,
                              void* d_out, int out_size) {
    const float* feat_row = (const float*)d_in[0];
    const float* feat_col = (const float*)d_in[1];
    const int*   src_c2r  = (const int*)d_in[2];
    const int*   dst_c2r  = (const int*)d_in[3];
    const float* w_c2r    = (const float*)d_in[4];
    const int*   src_r2c  = (const int*)d_in[5];
    const int*   dst_r2c  = (const int*)d_in[6];
    const float* w_r2c    = (const float*)d_in[7];
    const float* W1_c2r   = (const float*)d_in[8];
    const float* b1_c2r   = (const float*)d_in[9];
    const float* W2_c2r   = (const float*)d_in[10];
    const float* b2_c2r   = (const float*)d_in[11];
    const float* W1_r2c   = (const float*)d_in[12];
    const float* b1_r2c   = (const float*)d_in[13];
    const float* W2_r2c   = (const float*)d_in[14];
    const float* b2_r2c   = (const float*)d_in[15];
    const float* eps_c2r  = (const float*)d_in[16];
    const float* eps_r2c  = (const float*)d_in[17];

    const int E = in_sizes[2];

    float* out_row = (float*)d_out;
    float* out_col = out_row + (size_t)NROW * D;

    float *agg1, *agg2, *hrow;
    uint4* wt;
    int *cnt, *ptr, *cur, *bsum;
    int2* edges;
    cudaGetSymbolAddress((void**)&agg1,  g_agg1);
    cudaGetSymbolAddress((void**)&agg2,  g_agg2);
    cudaGetSymbolAddress((void**)&hrow,  g_hrow);
    cudaGetSymbolAddress((void**)&wt,    g_wt);
    cudaGetSymbolAddress((void**)&cnt,   g_cnt);
    cudaGetSymbolAddress((void**)&ptr,   g_ptr);
    cudaGetSymbolAddress((void**)&cur,   g_cur);
    cudaGetSymbolAddress((void**)&bsum,  g_bsum);
    cudaGetSymbolAddress((void**)&edges, g_edges);

    const uint4* w1hi_a = wt + 0 * WTILE_U4;
    const uint4* w1lo_a = wt + 1 * WTILE_U4;
    const uint4* w2hi_a = wt + 2 * WTILE_U4;
    const uint4* w2lo_a = wt + 3 * WTILE_U4;
    const uint4* w1hi_b = wt + 4 * WTILE_U4;
    const uint4* w1lo_b = wt + 5 * WTILE_U4;
    const uint4* w2hi_b = wt + 6 * WTILE_U4;
    const uint4* w2lo_b = wt + 7 * WTILE_U4;

    cudaFuncSetAttribute(mlp_tc_kernel, cudaFuncAttributeMaxDynamicSharedMemorySize, SM_TOTAL);

    const int egrid = (E + 255) / 256;
    const int g_row = (NROW + BM - 1) / BM;
    const int g_col = (NCOL + BM - 1) / BM;
    const int nscan_blocks = (NTOT + 1023) / 1024;     // 98
    const int agg_grid = (NROW * 32 + 255) / 256;      // 1 warp/node

    // ---- CSR build (both graphs jointly; independent of feature data) ----
    zero_cnt_kernel<<<(NTOT + 255) / 256, 256>>>(cnt, NTOT);
    hist_kernel<<<egrid, 256>>>(dst_c2r, cnt, E, 0);
    hist_kernel<<<egrid, 256>>>(dst_r2c, cnt, E, NROW);
    scan_blk_kernel<<<nscan_blocks, 1024>>>(cnt, ptr, bsum, NTOT);
    scan_tot_kernel<<<1, 128>>>(bsum, nscan_blocks);
    scan_add_kernel<<<(NTOT + 255) / 256, 256>>>(ptr, cur, bsum, NTOT, 2 * E);
    scatter_kernel<<<egrid, 256>>>(src_c2r, dst_c2r, w_c2r, cur, edges, E, 0);
    scatter_kernel<<<egrid, 256>>>(src_r2c, dst_r2c, w_r2c, cur, edges, E, NROW);
    split_w_kernel<<<32, 256>>>(W1_c2r, W2_c2r, W1_r2c, W2_r2c);

    // ---- col -> row ----
    csr_agg_kernel<<<agg_grid, 256>>>((const float4*)feat_col, ptr, edges, agg1, NROW, 0);
    mlp_tc_kernel<<<g_row, 256, SM_TOTAL>>>(feat_row, agg1, w1hi_a, w1lo_a, w2hi_a, w2lo_a,
                                            b1_c2r, b2_c2r, eps_c2r, hrow, out_row, NROW);
    // ---- row -> col (uses updated h_row) ----
    csr_agg_kernel<<<agg_grid, 256>>>((const float4*)hrow, ptr, edges, agg2, NCOL, NROW);
    mlp_tc_kernel<<<g_col, 256, SM_TOTAL>>>(feat_col, agg2, w1hi_b, w1lo_b, w2hi_b, w2lo_b,
                                            b1_r2c, b2_r2c, eps_r2c, nullptr, out_col, NCOL);
}

// round 9
// speedup vs baseline: 2.7844x; 1.0144x over previous
#include <cuda_runtime.h>
#include <cuda_bf16.h>
#include <cstdint>

#define D      128
#define NROW   50000
#define NCOL   50000
#define NTOT   (NROW + NCOL)
#define BM     64

// X tile: 64 rows x 128 k bf16, row stride 272B
#define LDB_B   272
#define XTILE_B (64 * LDB_B)          // 17408
// W half-tile: 128 n-rows x 64 k bf16, row stride 144B
#define LDW_B   144
#define WHALF_B (128 * LDW_B)         // 18432
#define WHALF_U4 (WHALF_B / 16)       // 1152

// Scratch (alloc-free rule: __device__ globals)
__device__ float g_agg1[(size_t)NROW * D];
__device__ float g_agg2[(size_t)NCOL * D];
__device__ float g_hrow[(size_t)NROW * D];
// [matrix 0..3][khalf 0..1][hi=0/lo=1][1152 uint4]
__device__ uint4 g_wt[4][2][2][WHALF_U4];
__device__ int   g_cnt[NTOT];
__device__ int   g_ptr[NTOT + 1];
__device__ int   g_cur[NTOT];
__device__ int   g_bsum[128];
__device__ int2  g_edges[1200000];

__device__ __forceinline__ float leaky(float v) { return v >= 0.f ? v : 0.01f * v; }

// ---------------- CSR build ----------------
__global__ void zero_cnt_kernel(int* __restrict__ cnt, int n) {
    int i = blockIdx.x * blockDim.x + threadIdx.x;
    if (i < n) cnt[i] = 0;
}

// both graphs in one launch: e < E -> graph1, else graph2 (+NROW offset)
__global__ void hist2_kernel(const int* __restrict__ dst1, const int* __restrict__ dst2,
                             int* __restrict__ cnt, int E) {
    int e = blockIdx.x * blockDim.x + threadIdx.x;
    if (e >= 2 * E) return;
    if (e < E) atomicAdd(cnt + __ldg(dst1 + e), 1);
    else       atomicAdd(cnt + NROW + __ldg(dst2 + e - E), 1);
}

__global__ void scan_blk_kernel(const int* __restrict__ cnt, int* __restrict__ ptr,
                                int* __restrict__ bsum, int n) {
    __shared__ int wsum[32];
    int tid = threadIdx.x, lane = tid & 31, wid = tid >> 5;
    int i = blockIdx.x * 1024 + tid;
    int x = (i < n) ? cnt[i] : 0;
    int v = x;
    #pragma unroll
    for (int o = 1; o < 32; o <<= 1) { int t = __shfl_up_sync(~0u, v, o); if (lane >= o) v += t; }
    if (lane == 31) wsum[wid] = v;
    __syncthreads();
    if (wid == 0) {
        int s = wsum[lane];
        #pragma unroll
        for (int o = 1; o < 32; o <<= 1) { int t = __shfl_up_sync(~0u, s, o); if (lane >= o) s += t; }
        wsum[lane] = s;
    }
    __syncthreads();
    int woff = wid ? wsum[wid - 1] : 0;
    if (i < n) ptr[i] = woff + v - x;
    if (tid == 1023) bsum[blockIdx.x] = wsum[31];
}

__global__ void scan_tot_kernel(int* __restrict__ bsum, int nb) {
    __shared__ int tmp[128];
    int tid = threadIdx.x;
    int x = (tid < nb) ? bsum[tid] : 0;
    tmp[tid] = x;
    __syncthreads();
    for (int o = 1; o < 128; o <<= 1) {
        int t = (tid >= o) ? tmp[tid - o] : 0;
        __syncthreads();
        tmp[tid] += t;
        __syncthreads();
    }
    if (tid < nb) bsum[tid] = tmp[tid] - x;
}

__global__ void scan_add_kernel(int* __restrict__ ptr, int* __restrict__ cur,
                                const int* __restrict__ bsum, int n, int total) {
    int i = blockIdx.x * blockDim.x + threadIdx.x;
    if (i < n) {
        int v = ptr[i] + bsum[i >> 10];
        ptr[i] = v;
        cur[i] = v;
    }
    if (i == 0) ptr[n] = total;
}

__global__ void scatter2_kernel(const int* __restrict__ src1, const int* __restrict__ dst1,
                                const float* __restrict__ w1,
                                const int* __restrict__ src2, const int* __restrict__ dst2,
                                const float* __restrict__ w2,
                                int* __restrict__ cur, int2* __restrict__ edges, int E) {
    int e = blockIdx.x * blockDim.x + threadIdx.x;
    if (e >= 2 * E) return;
    if (e < E) {
        int pos = atomicAdd(cur + __ldg(dst1 + e), 1);
        edges[pos] = make_int2(__ldg(src1 + e), __float_as_int(__ldg(w1 + e)));
    } else {
        int ee = e - E;
        int pos = atomicAdd(cur + NROW + __ldg(dst2 + ee), 1);
        edges[pos] = make_int2(__ldg(src2 + ee), __float_as_int(__ldg(w2 + ee)));
    }
}

// ---------------- CSR aggregation: one warp per dst node ----------------
__global__ void csr_agg_kernel(const float4* __restrict__ feat,
                               const int* __restrict__ ptr,
                               const int2* __restrict__ edges,
                               float* __restrict__ agg, int n, int off) {
    int t = blockIdx.x * blockDim.x + threadIdx.x;
    int node = t >> 5;
    if (node >= n) return;
    int lane = t & 31;
    int beg = __ldg(ptr + off + node);
    int end = __ldg(ptr + off + node + 1);
    float4 a0 = make_float4(0.f, 0.f, 0.f, 0.f);
    float4 a1 = make_float4(0.f, 0.f, 0.f, 0.f);
    int i = beg;
    for (; i + 2 <= end; i += 2) {
        int2 e0 = __ldg(edges + i);
        int2 e1 = __ldg(edges + i + 1);
        float w0 = __int_as_float(e0.y), w1 = __int_as_float(e1.y);
        float4 v0 = __ldg(feat + (size_t)e0.x * 32 + lane);
        float4 v1 = __ldg(feat + (size_t)e1.x * 32 + lane);
        a0.x = fmaf(v0.x, w0, a0.x); a0.y = fmaf(v0.y, w0, a0.y);
        a0.z = fmaf(v0.z, w0, a0.z); a0.w = fmaf(v0.w, w0, a0.w);
        a1.x = fmaf(v1.x, w1, a1.x); a1.y = fmaf(v1.y, w1, a1.y);
        a1.z = fmaf(v1.z, w1, a1.z); a1.w = fmaf(v1.w, w1, a1.w);
    }
    if (i < end) {
        int2 e0 = __ldg(edges + i);
        float w0 = __int_as_float(e0.y);
        float4 v0 = __ldg(feat + (size_t)e0.x * 32 + lane);
        a0.x = fmaf(v0.x, w0, a0.x); a0.y = fmaf(v0.y, w0, a0.y);
        a0.z = fmaf(v0.z, w0, a0.z); a0.w = fmaf(v0.w, w0, a0.w);
    }
    ((float4*)agg)[(size_t)node * 32 + lane] =
        make_float4(a0.x + a1.x, a0.y + a1.y, a0.z + a1.z, a0.w + a1.w);
}

// ---------------- weight pre-split ----------------
static __device__ __forceinline__ void split8(const float* x, uint32_t* hi, uint32_t* lo) {
    #pragma unroll
    for (int j = 0; j < 4; j++) {
        __nv_bfloat16 h0 = __float2bfloat16(x[2*j]);
        __nv_bfloat16 h1 = __float2bfloat16(x[2*j+1]);
        __nv_bfloat16 l0 = __float2bfloat16(x[2*j]   - __bfloat162float(h0));
        __nv_bfloat16 l1 = __float2bfloat16(x[2*j+1] - __bfloat162float(h1));
        hi[j] = (uint32_t)__bfloat16_as_ushort(h0) | ((uint32_t)__bfloat16_as_ushort(h1) << 16);
        lo[j] = (uint32_t)__bfloat16_as_ushort(l0) | ((uint32_t)__bfloat16_as_ushort(l1) << 16);
    }
}

static __device__ __forceinline__ void split2(float x0, float x1, uint32_t& hi, uint32_t& lo) {
    __nv_bfloat16 h0 = __float2bfloat16(x0);
    __nv_bfloat16 h1 = __float2bfloat16(x1);
    __nv_bfloat16 l0 = __float2bfloat16(x0 - __bfloat162float(h0));
    __nv_bfloat16 l1 = __float2bfloat16(x1 - __bfloat162float(h1));
    hi = (uint32_t)__bfloat16_as_ushort(h0) | ((uint32_t)__bfloat16_as_ushort(h1) << 16);
    lo = (uint32_t)__bfloat16_as_ushort(l0) | ((uint32_t)__bfloat16_as_ushort(l1) << 16);
}

// pre-split all 4 weight matrices into k-half tiles (transposed, final smem layout)
__global__ void split_w_kernel(const float* __restrict__ Wa, const float* __restrict__ Wb,
                               const float* __restrict__ Wc, const float* __restrict__ Wd) {
    int task = blockIdx.x * blockDim.x + threadIdx.x;   // 0..8191
    int m = task >> 11;
    int tt = task & 2047;
    int n = tt & 127, kg = tt >> 7;        // kg = k/8 (0..15)
    const float* W = (m == 0) ? Wa : (m == 1) ? Wb : (m == 2) ? Wc : Wd;
    float v[8];
    #pragma unroll
    for (int j = 0; j < 8; j++) v[j] = __ldg(W + (kg * 8 + j) * D + n);
    uint32_t hi[4], lo[4];
    split8(v, hi, lo);
    int half = kg >> 3, kgl = kg & 7;
    int idx = n * 9 + kgl;                 // (n*144 + kgl*16)/16
    g_wt[m][half][0][idx] = make_uint4(hi[0], hi[1], hi[2], hi[3]);
    g_wt[m][half][1][idx] = make_uint4(lo[0], lo[1], lo[2], lo[3]);
}

// ---------------- HMMA (mma.sync) MLP, pipelined W halves ----------------
#define SM_XHI  0
#define SM_XLO  (SM_XHI + XTILE_B)
#define SM_WS0  (SM_XLO + XTILE_B)        // half-slot 0 hi  (34816)
#define SM_WS1  (SM_WS0 + WHALF_B)        // half-slot 0 lo  (53248)
#define SM_WS2  (SM_WS1 + WHALF_B)        // half-slot 1 hi  (71680)
#define SM_WS3  (SM_WS2 + WHALF_B)        // half-slot 1 lo  (90112)
#define SM_B1   (SM_WS3 + WHALF_B)        // 108544
#define SM_B2   (SM_B1 + 512)
#define SM_TOTAL (SM_B2 + 512)            // 109568 -> 2 CTAs/SM
#define SM_FST  SM_WS0                    // epilogue fp32 staging (64*132*4=33792)
#define LDF     132

static __device__ __forceinline__ uint32_t smem_u32(const void* p) {
    uint32_t a;
    asm("{ .reg .u64 t; cvta.to.shared.u64 t, %1; cvt.u32.u64 %0, t; }" : "=r"(a) : "l"(p));
    return a;
}

static __device__ __forceinline__ void ldsm4(uint32_t* r, uint32_t addr) {
    asm volatile("ldmatrix.sync.aligned.m8n8.x4.shared.b16 {%0,%1,%2,%3}, [%4];"
                 : "=r"(r[0]), "=r"(r[1]), "=r"(r[2]), "=r"(r[3]) : "r"(addr));
}

static __device__ __forceinline__ void mma16816(float* d, const uint32_t* a,
                                                uint32_t b0, uint32_t b1) {
    asm volatile("mma.sync.aligned.m16n8k16.row.col.f32.bf16.bf16.f32 "
                 "{%0,%1,%2,%3}, {%4,%5,%6,%7}, {%8,%9}, {%0,%1,%2,%3};"
                 : "+f"(d[0]), "+f"(d[1]), "+f"(d[2]), "+f"(d[3])
                 : "r"(a[0]), "r"(a[1]), "r"(a[2]), "r"(a[3]), "r"(b0), "r"(b1));
}

// async copy one W half (hi+lo) into slot pair; one commit group
static __device__ __forceinline__ void stage_whalf(uint32_t smb, uint32_t hi_off, uint32_t lo_off,
                                                   const uint4* __restrict__ half_base, int tid) {
    const uint4* hi = half_base;
    const uint4* lo = half_base + WHALF_U4;
    for (int i = tid; i < WHALF_U4; i += 256) {
        asm volatile("cp.async.cg.shared.global [%0], [%1], 16;"
                     :: "r"(smb + hi_off + (uint32_t)i * 16), "l"(hi + i));
        asm volatile("cp.async.cg.shared.global [%0], [%1], 16;"
                     :: "r"(smb + lo_off + (uint32_t)i * 16), "l"(lo + i));
    }
    asm volatile("cp.async.commit_group;" ::: "memory");
}
template <int N>
static __device__ __forceinline__ void wait_cp_n() {
    asm volatile("cp.async.wait_group %0;" :: "n"(N) : "memory");
}

// one k-half of a layer: acc += X(m0.., k-half) @ Whalf^T over n [wn*64, +64)
static __device__ __forceinline__ void do_half(uint32_t smb, uint32_t whi, uint32_t wlo,
                                               int khalf, int m0, int wn, int lane,
                                               float acc[8][4]) {
    const int rsel = lane & 15;
    const uint32_t koff = (uint32_t)((lane >> 4) << 4);
    #pragma unroll
    for (int kk = 0; kk < 4; kk++) {
        uint32_t rowkA = (uint32_t)(khalf * 4 + kk) * 32 + koff;
        uint32_t rowkB = (uint32_t)kk * 32 + koff;
        uint32_t ahi[4], alo[4];
        ldsm4(ahi, smb + SM_XHI + (uint32_t)(m0 + rsel) * LDB_B + rowkA);
        ldsm4(alo, smb + SM_XLO + (uint32_t)(m0 + rsel) * LDB_B + rowkA);
        #pragma unroll
        for (int p = 0; p < 4; p++) {
            uint32_t boff = (uint32_t)((wn * 4 + p) * 16 + rsel) * LDW_B + rowkB;
            uint32_t bh[4], bl[4];
            ldsm4(bh, smb + whi + boff);
            ldsm4(bl, smb + wlo + boff);
            mma16816(acc[2*p],   ahi, bh[0], bh[2]);
            mma16816(acc[2*p+1], ahi, bh[1], bh[3]);
            mma16816(acc[2*p],   ahi, bl[0], bl[2]);
            mma16816(acc[2*p+1], ahi, bl[1], bl[3]);
            mma16816(acc[2*p],   alo, bh[0], bh[2]);
            mma16816(acc[2*p+1], alo, bh[1], bh[3]);
        }
    }
}

__global__ void __launch_bounds__(256, 2)
mlp_tc_kernel(const float* __restrict__ feat, const float* __restrict__ agg,
              const uint4* __restrict__ wmat1,   // [half][hi/lo][1152]
              const uint4* __restrict__ wmat2,
              const float* __restrict__ b1, const float* __restrict__ b2,
              const float* __restrict__ eps_p,
              float* __restrict__ h_out, float* __restrict__ out, int N) {
    extern __shared__ char sm[];
    const uint32_t smb = smem_u32(sm);
    const int tid = threadIdx.x;
    const int wid = tid >> 5;
    const int lane = tid & 31;
    const int m0 = (wid & 3) * 16;
    const int wn = wid >> 2;
    const int row0 = blockIdx.x * BM;
    const float eps1 = 1.f + __ldg(eps_p);

    const float4* feat4 = (const float4*)feat;
    const float4* agg4  = (const float4*)agg;
    float* sB1 = (float*)(sm + SM_B1);
    float* sB2 = (float*)(sm + SM_B2);

    // prefetch W1 (both halves, two groups) under X staging
    stage_whalf(smb, SM_WS0, SM_WS1, wmat1, tid);                 // group: W1h1
    stage_whalf(smb, SM_WS2, SM_WS3, wmat1 + 2 * WHALF_U4, tid);  // group: W1h2

    if (tid < 128) {
        sB1[tid] = __ldg(b1 + tid);
        sB2[tid] = __ldg(b2 + tid);
    }

    // ---- stage x = (1+eps)*feat + agg as bf16 hi/lo (64 rows) ----
    #pragma unroll
    for (int i = 0; i < 4; i++) {
        int tt = tid + i * 256;
        int tr = tt >> 4, kg = tt & 15;
        int grow = row0 + tr;
        float v[8];
        if (grow < N) {
            float4 f0 = __ldg(feat4 + (size_t)grow * 32 + kg * 2);
            float4 f1 = __ldg(feat4 + (size_t)grow * 32 + kg * 2 + 1);
            float4 a0 = __ldg(agg4  + (size_t)grow * 32 + kg * 2);
            float4 a1 = __ldg(agg4  + (size_t)grow * 32 + kg * 2 + 1);
            v[0] = fmaf(eps1, f0.x, a0.x); v[1] = fmaf(eps1, f0.y, a0.y);
            v[2] = fmaf(eps1, f0.z, a0.z); v[3] = fmaf(eps1, f0.w, a0.w);
            v[4] = fmaf(eps1, f1.x, a1.x); v[5] = fmaf(eps1, f1.y, a1.y);
            v[6] = fmaf(eps1, f1.z, a1.z); v[7] = fmaf(eps1, f1.w, a1.w);
        } else {
            #pragma unroll
            for (int j = 0; j < 8; j++) v[j] = 0.f;
        }
        uint32_t hi[4], lo[4];
        split8(v, hi, lo);
        uint32_t off = (uint32_t)tr * LDB_B + (uint32_t)kg * 16;
        *(uint4*)(sm + SM_XHI + off) = make_uint4(hi[0], hi[1], hi[2], hi[3]);
        *(uint4*)(sm + SM_XLO + off) = make_uint4(lo[0], lo[1], lo[2], lo[3]);
    }

    float acc[8][4];
    #pragma unroll
    for (int t = 0; t < 8; t++)
        #pragma unroll
        for (int j = 0; j < 4; j++) acc[t][j] = 0.f;

    wait_cp_n<1>();          // W1h1 arrived (W1h2 may be in flight)
    __syncthreads();

    // ---- L1 half a (k 0..63) ----
    do_half(smb, SM_WS0, SM_WS1, 0, m0, wn, lane, acc);

    wait_cp_n<0>();          // W1h2 arrived
    __syncthreads();         // all warps done reading W1h1 slots
    // stream W2h1 into the dead W1h1 slots while L1b computes
    stage_whalf(smb, SM_WS0, SM_WS1, wmat2, tid);

    // ---- L1 half b (k 64..127) ----
    do_half(smb, SM_WS2, SM_WS3, 1, m0, wn, lane, acc);
    __syncthreads();         // all warps done reading X (and W1h2)

    // writeback h1 = leaky(acc + b1) into X tiles (gives W2h1 copy time)
    {
        const int r0 = m0 + (lane >> 2);
        const int c0 = 2 * (lane & 3);
        #pragma unroll
        for (int p = 0; p < 4; p++) {
            #pragma unroll
            for (int s = 0; s < 2; s++) {
                int c = (wn * 4 + p) * 16 + s * 8 + c0;
                float v0 = leaky(acc[2*p+s][0] + sB1[c]);
                float v1 = leaky(acc[2*p+s][1] + sB1[c + 1]);
                float v2 = leaky(acc[2*p+s][2] + sB1[c]);
                float v3 = leaky(acc[2*p+s][3] + sB1[c + 1]);
                uint32_t h01, l01, h23, l23;
                split2(v0, v1, h01, l01);
                split2(v2, v3, h23, l23);
                uint32_t o0 = (uint32_t)r0 * LDB_B + (uint32_t)c * 2;
                uint32_t o1 = o0 + 8u * LDB_B;
                *(uint32_t*)(sm + SM_XHI + o0) = h01;
                *(uint32_t*)(sm + SM_XLO + o0) = l01;
                *(uint32_t*)(sm + SM_XHI + o1) = h23;
                *(uint32_t*)(sm + SM_XLO + o1) = l23;
            }
        }
    }

    #pragma unroll
    for (int t = 0; t < 8; t++)
        #pragma unroll
        for (int j = 0; j < 4; j++) acc[t][j] = 0.f;

    wait_cp_n<0>();          // W2h1 arrived
    __syncthreads();         // h1 writeback visible; W2h1 visible
    // stream W2h2 into the dead W1h2 slots while L2a computes
    stage_whalf(smb, SM_WS2, SM_WS3, wmat2 + 2 * WHALF_U4, tid);

    // ---- L2 half a ----
    do_half(smb, SM_WS0, SM_WS1, 0, m0, wn, lane, acc);

    wait_cp_n<0>();          // W2h2 arrived
    __syncthreads();
    // ---- L2 half b ----
    do_half(smb, SM_WS2, SM_WS3, 1, m0, wn, lane, acc);

    // epilogue: FST (= WS0/WS1 region, read only in L2a which all warps passed)
    {
        float* fst = (float*)(sm + SM_FST);
        const int r0 = m0 + (lane >> 2);
        const int c0 = 2 * (lane & 3);
        #pragma unroll
        for (int p = 0; p < 4; p++) {
            #pragma unroll
            for (int s = 0; s < 2; s++) {
                int c = (wn * 4 + p) * 16 + s * 8 + c0;
                float v0 = leaky(acc[2*p+s][0] + sB2[c]);
                float v1 = leaky(acc[2*p+s][1] + sB2[c + 1]);
                float v2 = leaky(acc[2*p+s][2] + sB2[c]);
                float v3 = leaky(acc[2*p+s][3] + sB2[c + 1]);
                *(float2*)(fst + (size_t)r0 * LDF + c)       = make_float2(v0, v1);
                *(float2*)(fst + (size_t)(r0 + 8) * LDF + c) = make_float2(v2, v3);
            }
        }
    }
    __syncthreads();

    // coalesced final writes: out = h2 + feat; h_out = h2
    {
        const float* fst = (const float*)(sm + SM_FST);
        #pragma unroll
        for (int i = 0; i < 8; i++) {
            int idx = tid + i * 256;
            int r = idx >> 5, c4 = idx & 31;
            int grow = row0 + r;
            if (grow >= N) continue;
            const float* p = fst + (size_t)r * LDF + c4 * 4;
            float4 h = make_float4(p[0], p[1], p[2], p[3]);
            float4 fv = __ldg(feat4 + (size_t)grow * 32 + c4);
            ((float4*)out)[(size_t)grow * 32 + c4] =
                make_float4(h.x + fv.x, h.y + fv.y, h.z + fv.z, h.w + fv.w);
            if (h_out)
                ((float4*)h_out)[(size_t)grow * 32 + c4] = h;
        }
    }
}

extern "C" void kernel_launch(void* const* d_in, const int* in_sizes, int n_in,
                              void* d_out, int out_size) {
    const float* feat_row = (const float*)d_in[0];
    const float* feat_col = (const float*)d_in[1];
    const int*   src_c2r  = (const int*)d_in[2];
    const int*   dst_c2r  = (const int*)d_in[3];
    const float* w_c2r    = (const float*)d_in[4];
    const int*   src_r2c  = (const int*)d_in[5];
    const int*   dst_r2c  = (const int*)d_in[6];
    const float* w_r2c    = (const float*)d_in[7];
    const float* W1_c2r   = (const float*)d_in[8];
    const float* b1_c2r   = (const float*)d_in[9];
    const float* W2_c2r   = (const float*)d_in[10];
    const float* b2_c2r   = (const float*)d_in[11];
    const float* W1_r2c   = (const float*)d_in[12];
    const float* b1_r2c   = (const float*)d_in[13];
    const float* W2_r2c   = (const float*)d_in[14];
    const float* b2_r2c   = (const float*)d_in[15];
    const float* eps_c2r  = (const float*)d_in[16];
    const float* eps_r2c  = (const float*)d_in[17];

    const int E = in_sizes[2];

    float* out_row = (float*)d_out;
    float* out_col = out_row + (size_t)NROW * D;

    float *agg1, *agg2, *hrow;
    uint4* wt;
    int *cnt, *ptr, *cur, *bsum;
    int2* edges;
    cudaGetSymbolAddress((void**)&agg1,  g_agg1);
    cudaGetSymbolAddress((void**)&agg2,  g_agg2);
    cudaGetSymbolAddress((void**)&hrow,  g_hrow);
    cudaGetSymbolAddress((void**)&wt,    g_wt);
    cudaGetSymbolAddress((void**)&cnt,   g_cnt);
    cudaGetSymbolAddress((void**)&ptr,   g_ptr);
    cudaGetSymbolAddress((void**)&cur,   g_cur);
    cudaGetSymbolAddress((void**)&bsum,  g_bsum);
    cudaGetSymbolAddress((void**)&edges, g_edges);

    // per matrix: 2 halves x 2 (hi/lo) x 1152 uint4
    const int MAT_U4 = 2 * 2 * WHALF_U4;
    const uint4* w1_a = wt + 0 * MAT_U4;
    const uint4* w2_a = wt + 1 * MAT_U4;
    const uint4* w1_b = wt + 2 * MAT_U4;
    const uint4* w2_b = wt + 3 * MAT_U4;

    cudaFuncSetAttribute(mlp_tc_kernel, cudaFuncAttributeMaxDynamicSharedMemorySize, SM_TOTAL);

    const int e2grid = (2 * E + 255) / 256;
    const int g_row = (NROW + BM - 1) / BM;
    const int g_col = (NCOL + BM - 1) / BM;
    const int nscan_blocks = (NTOT + 1023) / 1024;
    const int agg_grid = (NROW * 32 + 255) / 256;

    // ---- CSR build (both graphs jointly) ----
    zero_cnt_kernel<<<(NTOT + 255) / 256, 256>>>(cnt, NTOT);
    hist2_kernel<<<e2grid, 256>>>(dst_c2r, dst_r2c, cnt, E);
    scan_blk_kernel<<<nscan_blocks, 1024>>>(cnt, ptr, bsum, NTOT);
    scan_tot_kernel<<<1, 128>>>(bsum, nscan_blocks);
    scan_add_kernel<<<(NTOT + 255) / 256, 256>>>(ptr, cur, bsum, NTOT, 2 * E);
    scatter2_kernel<<<e2grid, 256>>>(src_c2r, dst_c2r, w_c2r, src_r2c, dst_r2c, w_r2c,
                                     cur, edges, E);
    split_w_kernel<<<32, 256>>>(W1_c2r, W2_c2r, W1_r2c, W2_r2c);

    // ---- col -> row ----
    csr_agg_kernel<<<agg_grid, 256>>>((const float4*)feat_col, ptr, edges, agg1, NROW, 0);
    mlp_tc_kernel<<<g_row, 256, SM_TOTAL>>>(feat_row, agg1, w1_a, w2_a,
                                            b1_c2r, b2_c2r, eps_c2r, hrow, out_row, NROW);
    // ---- row -> col (uses updated h_row) ----
    csr_agg_kernel<<<agg_grid, 256>>>((const float4*)hrow, ptr, edges, agg2, NCOL, NROW);
    mlp_tc_kernel<<<g_col, 256, SM_TOTAL>>>(feat_col, agg2, w1_b, w2_b,
                                            b1_r2c, b2_r2c, eps_r2c, nullptr, out_col, NCOL);
}